// round 6
// baseline (speedup 1.0000x reference)
#include <cuda_runtime.h>
#include <cuda_bf16.h>
#include <cstdint>
#include <math.h>

// Problem constants
#define B_     4096
#define D_     784
#define HALF_  392
#define HID_   512
#define CONDN_ 10
#define NBLK_  20

#define K1PAD  416          // 392 padded to 13*32
#define K2PAD  512
#define N2PAD  896          // 448 (s,t)-pairs * 2

// GEMM tiling: CTA 128(M) x 64(N) x 32(K-stage), 8 warps of 32x32, 3-stage pipeline
#define TILE_M 128
#define TILE_N 64
#define TILE_K 32
#define STAGES 3

// smem stage layout (bytes): rows padded 64B->80B for conflict-free ldmatrix
#define SA_ROW   80
#define ST_AHI   0
#define ST_ALO   10240
#define ST_BHI   20480
#define ST_BLO   25600
#define ST_SIZE  30720
#define SM_TOTAL (STAGES * ST_SIZE)

// ---------------- PTX helpers ----------------
__device__ __forceinline__ uint32_t smem_u32(const void* p) {
    uint32_t a;
    asm("{ .reg .u64 t; cvta.to.shared.u64 t, %1; cvt.u32.u64 %0, t; }" : "=r"(a) : "l"(p));
    return a;
}
#define CP_ASYNC16(dst, src) \
    asm volatile("cp.async.cg.shared.global [%0], [%1], 16;" :: "r"(dst), "l"(src))
#define CP_COMMIT() asm volatile("cp.async.commit_group;" ::: "memory")
#define CP_WAIT1()  asm volatile("cp.async.wait_group 1;" ::: "memory")

__device__ __forceinline__ void ldm4(uint32_t& r0, uint32_t& r1, uint32_t& r2, uint32_t& r3,
                                     uint32_t a) {
    asm volatile("ldmatrix.sync.aligned.m8n8.x4.shared.b16 {%0,%1,%2,%3}, [%4];"
                 : "=r"(r0), "=r"(r1), "=r"(r2), "=r"(r3) : "r"(a));
}
__device__ __forceinline__ void mma_bf16(float& c0, float& c1, float& c2, float& c3,
                                         uint32_t a0, uint32_t a1, uint32_t a2, uint32_t a3,
                                         uint32_t b0, uint32_t b1) {
    asm volatile(
        "mma.sync.aligned.m16n8k16.row.col.f32.bf16.bf16.f32 "
        "{%0,%1,%2,%3}, {%4,%5,%6,%7}, {%8,%9}, {%0,%1,%2,%3};"
        : "+f"(c0), "+f"(c1), "+f"(c2), "+f"(c3)
        : "r"(a0), "r"(a1), "r"(a2), "r"(a3), "r"(b0), "r"(b1));
}

// ---------------- device scratch ----------------
// ping-pong (by block parity) permuted activations
__device__ float g_xa[2 * B_ * HALF_];
__device__ float g_xb[2 * B_ * HALF_];
__device__ __nv_bfloat16 g_xbh[2 * B_ * K1PAD];
__device__ __nv_bfloat16 g_xbl[2 * B_ * K1PAD];
// within-block buffers
__device__ __nv_bfloat16 g_ysh[B_ * K1PAD];
__device__ __nv_bfloat16 g_ysl[B_ * K1PAD];
__device__ __nv_bfloat16 g_hh [B_ * K2PAD];
__device__ __nv_bfloat16 g_hl [B_ * K2PAD];
// inverse permutations
__device__ int g_inv[NBLK_ * D_];

// transposed + split weights: W1t [blk][512][416], W2t interleaved [blk][896][512]
__device__ __nv_bfloat16 g_s1w1_hi[NBLK_ * HID_ * K1PAD];
__device__ __nv_bfloat16 g_s1w1_lo[NBLK_ * HID_ * K1PAD];
__device__ __nv_bfloat16 g_s2w1_hi[NBLK_ * HID_ * K1PAD];
__device__ __nv_bfloat16 g_s2w1_lo[NBLK_ * HID_ * K1PAD];
__device__ __nv_bfloat16 g_s1w2_hi[NBLK_ * N2PAD * K2PAD];
__device__ __nv_bfloat16 g_s1w2_lo[NBLK_ * N2PAD * K2PAD];
__device__ __nv_bfloat16 g_s2w2_hi[NBLK_ * N2PAD * K2PAD];
__device__ __nv_bfloat16 g_s2w2_lo[NBLK_ * N2PAD * K2PAD];

__device__ __forceinline__ void split1(float v, __nv_bfloat16& h, __nv_bfloat16& l) {
    h = __float2bfloat16_rn(v);
    l = __float2bfloat16_rn(v - __bfloat162float(h));
}

// ---------------- small kernels ----------------
// zero jac; zero K-pad columns of all split activation buffers; build inverse perms
__global__ void init_kernel(const int* __restrict__ perms, float* __restrict__ jac,
                            __nv_bfloat16* __restrict__ xbh, __nv_bfloat16* __restrict__ xbl,
                            __nv_bfloat16* __restrict__ ysh, __nv_bfloat16* __restrict__ ysl,
                            int* __restrict__ inv) {
    int idx = blockIdx.x * blockDim.x + threadIdx.x;
    if (idx < B_) jac[idx] = 0.f;
    if (idx < NBLK_ * D_) {
        int k = idx / D_;
        int j = idx - k * D_;
        inv[k * D_ + perms[idx]] = j;
    }
    if (idx < B_ * (K1PAD - HALF_)) {
        int i = idx / (K1PAD - HALF_);
        int jj = HALF_ + idx % (K1PAD - HALF_);
        __nv_bfloat16 zz = __float2bfloat16_rn(0.f);
        size_t o = (size_t)i * K1PAD + jj;
        size_t o2 = o + (size_t)B_ * K1PAD;
        xbh[o] = zz; xbl[o] = zz; xbh[o2] = zz; xbl[o2] = zz;
        ysh[o] = zz; ysl[o] = zz;
    }
}

// block-0 permute + split second half (parity 0 buffers)
__global__ void permute_kernel(const float* __restrict__ v,
                               const int* __restrict__ perm,
                               float* __restrict__ xa,
                               float* __restrict__ xb,
                               __nv_bfloat16* __restrict__ xbh,
                               __nv_bfloat16* __restrict__ xbl) {
    int idx = blockIdx.x * blockDim.x + threadIdx.x;
    if (idx >= B_ * D_) return;
    int i = idx / D_;
    int j = idx - i * D_;
    float val = v[(size_t)i * D_ + perm[j]];
    if (j < HALF_) {
        xa[(size_t)i * HALF_ + j] = val;
    } else {
        int jj = j - HALF_;
        xb[(size_t)i * HALF_ + jj] = val;
        __nv_bfloat16 h, l;
        split1(val, h, l);
        xbh[(size_t)i * K1PAD + jj] = h;
        xbl[(size_t)i * K1PAD + jj] = l;
    }
}

// transpose + split W1 (both subnets via grid.z): [blk][402][512] -> [blk][512][416]
__global__ void convert_w1_kernel(const float* __restrict__ Ws1, const float* __restrict__ Ws2,
                                  __nv_bfloat16* __restrict__ hi1, __nv_bfloat16* __restrict__ lo1,
                                  __nv_bfloat16* __restrict__ hi2, __nv_bfloat16* __restrict__ lo2) {
    __shared__ float t[16][17];
    int zz = blockIdx.z;
    int sel = zz >= NBLK_;
    int blk = sel ? zz - NBLK_ : zz;
    const float* W = sel ? Ws2 : Ws1;
    __nv_bfloat16* hi = sel ? hi2 : hi1;
    __nv_bfloat16* lo = sel ? lo2 : lo1;
    int bk = blockIdx.x;
    int bn = blockIdx.y;
    int tx = threadIdx.x & 15, ty = threadIdx.x >> 4;
    int k = bk * 16 + ty, n = bn * 16 + tx;
    float v = (k < HALF_) ? W[((size_t)blk * (HALF_ + CONDN_) + k) * HID_ + n] : 0.f;
    t[ty][tx] = v;
    __syncthreads();
    float o = t[tx][ty];
    __nv_bfloat16 h, l;
    split1(o, h, l);
    size_t oidx = ((size_t)blk * HID_ + bn * 16 + ty) * K1PAD + bk * 16 + tx;
    hi[oidx] = h;
    lo[oidx] = l;
}

// transpose + split + (s,t)-interleave W2: [blk][512][784] -> [blk][896][512]
__global__ void convert_w2_kernel(const float* __restrict__ Ws1, const float* __restrict__ Ws2,
                                  __nv_bfloat16* __restrict__ hi1, __nv_bfloat16* __restrict__ lo1,
                                  __nv_bfloat16* __restrict__ hi2, __nv_bfloat16* __restrict__ lo2) {
    __shared__ float t[16][17];
    int zz = blockIdx.z;
    int sel = zz >= NBLK_;
    int blk = sel ? zz - NBLK_ : zz;
    const float* W = sel ? Ws2 : Ws1;
    __nv_bfloat16* hi = sel ? hi2 : hi1;
    __nv_bfloat16* lo = sel ? lo2 : lo1;
    int bk = blockIdx.x;
    int bn = blockIdx.y;
    int tx = threadIdx.x & 15, ty = threadIdx.x >> 4;
    int k = bk * 16 + ty;
    int nOut = bn * 16 + tx;
    int p = nOut >> 1;
    int orig = (nOut & 1) ? (HALF_ + p) : p;
    float v = (p < HALF_) ? W[((size_t)blk * HID_ + k) * D_ + orig] : 0.f;
    t[ty][tx] = v;
    __syncthreads();
    float o = t[tx][ty];
    __nv_bfloat16 h, l;
    split1(o, h, l);
    size_t oidx = ((size_t)blk * N2PAD + bn * 16 + ty) * K2PAD + bk * 16 + tx;
    hi[oidx] = h;
    lo[oidx] = l;
}

// ---------------- fused HMMA GEMM ----------------
// MODE 0: hidden layer. C = relu(A@Bt^T + bias + Wcond[392+lab[m]]), write split bf16 (Chi/Clo).
// MODE 1/2: output layer with interleaved (s,t) columns, fused coupling:
//   p = n/2; s = acc(n)+bias[p]; t = acc(n+1)+bias[392+p];
//   ls = 0.636*atan(s); y = exp(ls)*xo[m][p] + t; jac[m] += ls;
//   MODE 1 additionally writes split bf16 y natural-order (Chi/Clo, for next hidden GEMM).
//   PERM: scatter y to next block's permuted buffers via j=invp[p]
//         (j<392 -> xaN fp32; else xbN fp32 + split xbNh/xbNl).
//   !PERM: write y fp32 natural to Yf (stride D_).
template<int MODE, bool PERM>
__global__ __launch_bounds__(256, 2)
void gemm_mma(const __nv_bfloat16* __restrict__ Ahi, const __nv_bfloat16* __restrict__ Alo,
              const __nv_bfloat16* __restrict__ Bhi, const __nv_bfloat16* __restrict__ Blo,
              int Ka, int nch,
              const float* __restrict__ bias,
              const float* __restrict__ Wcond, const int* __restrict__ lab,
              const float* __restrict__ xo,
              float* __restrict__ Yf, float* __restrict__ jac,
              __nv_bfloat16* __restrict__ Chi, __nv_bfloat16* __restrict__ Clo,
              const int* __restrict__ invp,
              float* __restrict__ xaN, float* __restrict__ xbN,
              __nv_bfloat16* __restrict__ xbNh, __nv_bfloat16* __restrict__ xbNl) {
    extern __shared__ __align__(128) char sm[];
    const int tid = threadIdx.x;
    const int lane = tid & 31, wid = tid >> 5;
    const int wm = wid & 3, wn = wid >> 2;           // 4x2 warp grid, 32x32 warp tiles
    const int m0 = blockIdx.y * TILE_M, n0 = blockIdx.x * TILE_N;
    const uint32_t sb = smem_u32(sm);

    // cp.async maps
    const int a_row = tid >> 2, a_seg = tid & 3;     // A: rows 0..63 (+64), 4 segs of 16B
    const int b_row = tid >> 2, b_seg = tid & 3;     // B: rows 0..63

    float acc[2][4][4];
#pragma unroll
    for (int i = 0; i < 2; i++)
#pragma unroll
        for (int j = 0; j < 4; j++)
#pragma unroll
            for (int q = 0; q < 4; q++) acc[i][j][q] = 0.f;

#define LOAD_STAGE(c, s)                                                                  \
    do {                                                                                  \
        uint32_t st = sb + (s) * ST_SIZE;                                                 \
        const __nv_bfloat16* a0s = Ahi + (size_t)(m0 + a_row) * Ka + (c) * 32 + a_seg * 8;\
        const __nv_bfloat16* a1s = a0s + (size_t)64 * Ka;                                 \
        const __nv_bfloat16* a2s = Alo + (size_t)(m0 + a_row) * Ka + (c) * 32 + a_seg * 8;\
        const __nv_bfloat16* a3s = a2s + (size_t)64 * Ka;                                 \
        CP_ASYNC16(st + ST_AHI + a_row * SA_ROW + a_seg * 16, a0s);                       \
        CP_ASYNC16(st + ST_AHI + (a_row + 64) * SA_ROW + a_seg * 16, a1s);                \
        CP_ASYNC16(st + ST_ALO + a_row * SA_ROW + a_seg * 16, a2s);                       \
        CP_ASYNC16(st + ST_ALO + (a_row + 64) * SA_ROW + a_seg * 16, a3s);                \
        CP_ASYNC16(st + ST_BHI + b_row * SA_ROW + b_seg * 16,                             \
                   Bhi + (size_t)(n0 + b_row) * Ka + (c) * 32 + b_seg * 8);               \
        CP_ASYNC16(st + ST_BLO + b_row * SA_ROW + b_seg * 16,                             \
                   Blo + (size_t)(n0 + b_row) * Ka + (c) * 32 + b_seg * 8);               \
    } while (0)

    LOAD_STAGE(0, 0);
    CP_COMMIT();
    LOAD_STAGE(1, 1);
    CP_COMMIT();

    // ldmatrix lane address components
    const uint32_t a_lrow = (lane & 15);
    const uint32_t a_lcol = (lane >> 4) << 4;                       // 0 or 16 bytes
    const uint32_t b_lrow = (lane & 7) + ((lane & 16) >> 1);        // 0..15
    const uint32_t b_lcol = (lane & 8) << 1;                        // 0 or 16 bytes

    int cs = 0, ls2 = 2;
    for (int c = 0; c < nch; c++) {
        CP_WAIT1();            // stage c resident
        __syncthreads();       // all warps done with stage (c-1) compute; safe to overwrite
        if (c + 2 < nch) LOAD_STAGE(c + 2, ls2);
        CP_COMMIT();

        uint32_t st = sb + cs * ST_SIZE;
#pragma unroll
        for (int s = 0; s < 2; s++) {
            uint32_t a[2][2][4];   // [hl][mm][4]
            uint32_t b[2][4][2];   // [hl][n8][2]
#pragma unroll
            for (int hl = 0; hl < 2; hl++) {
#pragma unroll
                for (int mm = 0; mm < 2; mm++) {
                    uint32_t ad = st + (hl ? ST_ALO : ST_AHI)
                                + (wm * 32 + mm * 16 + a_lrow) * SA_ROW + a_lcol + s * 32;
                    ldm4(a[hl][mm][0], a[hl][mm][1], a[hl][mm][2], a[hl][mm][3], ad);
                }
#pragma unroll
                for (int nt = 0; nt < 2; nt++) {
                    uint32_t bd = st + (hl ? ST_BLO : ST_BHI)
                                + (wn * 32 + nt * 16 + b_lrow) * SA_ROW + b_lcol + s * 32;
                    ldm4(b[hl][2 * nt][0], b[hl][2 * nt][1],
                         b[hl][2 * nt + 1][0], b[hl][2 * nt + 1][1], bd);
                }
            }
#pragma unroll
            for (int mm = 0; mm < 2; mm++) {
#pragma unroll
                for (int nn = 0; nn < 4; nn++) {
                    float* cc = acc[mm][nn];
                    mma_bf16(cc[0], cc[1], cc[2], cc[3],
                             a[0][mm][0], a[0][mm][1], a[0][mm][2], a[0][mm][3],
                             b[0][nn][0], b[0][nn][1]);
                    mma_bf16(cc[0], cc[1], cc[2], cc[3],
                             a[0][mm][0], a[0][mm][1], a[0][mm][2], a[0][mm][3],
                             b[1][nn][0], b[1][nn][1]);
                    mma_bf16(cc[0], cc[1], cc[2], cc[3],
                             a[1][mm][0], a[1][mm][1], a[1][mm][2], a[1][mm][3],
                             b[0][nn][0], b[0][nn][1]);
                }
            }
        }
        cs = (cs == STAGES - 1) ? 0 : cs + 1;
        ls2 = (ls2 == STAGES - 1) ? 0 : ls2 + 1;
    }
#undef LOAD_STAGE

    // ---- epilogue ----
    const int rbase = lane >> 2;
    const int cbase = (lane & 3) * 2;

    if (MODE == 0) {
#pragma unroll
        for (int mm = 0; mm < 2; mm++) {
#pragma unroll
            for (int h = 0; h < 2; h++) {
                int m = m0 + wm * 32 + mm * 16 + rbase + h * 8;
                const float* wc = Wcond + (size_t)(HALF_ + lab[m]) * HID_;
#pragma unroll
                for (int nn = 0; nn < 4; nn++) {
                    int n = n0 + wn * 32 + nn * 8 + cbase;
                    float v0 = acc[mm][nn][h * 2 + 0] + bias[n] + wc[n];
                    float v1 = acc[mm][nn][h * 2 + 1] + bias[n + 1] + wc[n + 1];
                    v0 = fmaxf(v0, 0.f);
                    v1 = fmaxf(v1, 0.f);
                    __nv_bfloat16 h0, l0, h1, l1;
                    split1(v0, h0, l0);
                    split1(v1, h1, l1);
                    __nv_bfloat162 hp; hp.x = h0; hp.y = h1;
                    __nv_bfloat162 lp; lp.x = l0; lp.y = l1;
                    *reinterpret_cast<__nv_bfloat162*>(Chi + (size_t)m * HID_ + n) = hp;
                    *reinterpret_cast<__nv_bfloat162*>(Clo + (size_t)m * HID_ + n) = lp;
                }
            }
        }
    } else {
#pragma unroll
        for (int mm = 0; mm < 2; mm++) {
#pragma unroll
            for (int h = 0; h < 2; h++) {
                int m = m0 + wm * 32 + mm * 16 + rbase + h * 8;
                float jl = 0.f;
#pragma unroll
                for (int nn = 0; nn < 4; nn++) {
                    int n = n0 + wn * 32 + nn * 8 + cbase;   // always even
                    int p = n >> 1;
                    if (p < HALF_) {
                        float s = acc[mm][nn][h * 2 + 0] + bias[p];
                        float t = acc[mm][nn][h * 2 + 1] + bias[HALF_ + p];
                        float ls = 0.636f * atanf(s);
                        float y = expf(ls) * xo[(size_t)m * HALF_ + p] + t;
                        if (MODE == 1) {
                            __nv_bfloat16 yhh, yll;
                            split1(y, yhh, yll);
                            Chi[(size_t)m * K1PAD + p] = yhh;
                            Clo[(size_t)m * K1PAD + p] = yll;
                        }
                        if (PERM) {
                            int j = invp[p];
                            if (j < HALF_) {
                                xaN[(size_t)m * HALF_ + j] = y;
                            } else {
                                int jj = j - HALF_;
                                xbN[(size_t)m * HALF_ + jj] = y;
                                __nv_bfloat16 yhh, yll;
                                split1(y, yhh, yll);
                                xbNh[(size_t)m * K1PAD + jj] = yhh;
                                xbNl[(size_t)m * K1PAD + jj] = yll;
                            }
                        } else {
                            Yf[(size_t)m * D_ + p] = y;
                        }
                        jl += ls;
                    }
                }
                jl += __shfl_xor_sync(0xffffffffu, jl, 1);
                jl += __shfl_xor_sync(0xffffffffu, jl, 2);
                if ((lane & 3) == 0) atomicAdd(&jac[m], jl);
            }
        }
    }
}

// ---------------- host launcher ----------------
extern "C" void kernel_launch(void* const* d_in, const int* in_sizes, int n_in,
                              void* d_out, int out_size) {
    const float* x     = (const float*)d_in[0];
    const int*   l     = (const int*)  d_in[1];
    const int*   perms = (const int*)  d_in[2];
    const float* s1_W1 = (const float*)d_in[3];
    const float* s1_b1 = (const float*)d_in[4];
    const float* s1_W2 = (const float*)d_in[5];
    const float* s1_b2 = (const float*)d_in[6];
    const float* s2_W1 = (const float*)d_in[7];
    const float* s2_b1 = (const float*)d_in[8];
    const float* s2_W2 = (const float*)d_in[9];
    const float* s2_b2 = (const float*)d_in[10];

    float* z   = (float*)d_out;
    float* jac = z + (size_t)B_ * D_;

    float *pxa, *pxb;
    cudaGetSymbolAddress((void**)&pxa, g_xa);
    cudaGetSymbolAddress((void**)&pxb, g_xb);

    __nv_bfloat16 *xbh, *xbl, *ysh, *ysl, *hh, *hl;
    cudaGetSymbolAddress((void**)&xbh, g_xbh);
    cudaGetSymbolAddress((void**)&xbl, g_xbl);
    cudaGetSymbolAddress((void**)&ysh, g_ysh);
    cudaGetSymbolAddress((void**)&ysl, g_ysl);
    cudaGetSymbolAddress((void**)&hh,  g_hh);
    cudaGetSymbolAddress((void**)&hl,  g_hl);

    int* inv;
    cudaGetSymbolAddress((void**)&inv, g_inv);

    __nv_bfloat16 *w1h[2], *w1l[2], *w2h[2], *w2l[2];
    cudaGetSymbolAddress((void**)&w1h[0], g_s1w1_hi);
    cudaGetSymbolAddress((void**)&w1l[0], g_s1w1_lo);
    cudaGetSymbolAddress((void**)&w1h[1], g_s2w1_hi);
    cudaGetSymbolAddress((void**)&w1l[1], g_s2w1_lo);
    cudaGetSymbolAddress((void**)&w2h[0], g_s1w2_hi);
    cudaGetSymbolAddress((void**)&w2l[0], g_s1w2_lo);
    cudaGetSymbolAddress((void**)&w2h[1], g_s2w2_hi);
    cudaGetSymbolAddress((void**)&w2l[1], g_s2w2_lo);

    cudaFuncSetAttribute(gemm_mma<0, false>, cudaFuncAttributeMaxDynamicSharedMemorySize, SM_TOTAL);
    cudaFuncSetAttribute(gemm_mma<1, true >, cudaFuncAttributeMaxDynamicSharedMemorySize, SM_TOTAL);
    cudaFuncSetAttribute(gemm_mma<1, false>, cudaFuncAttributeMaxDynamicSharedMemorySize, SM_TOTAL);
    cudaFuncSetAttribute(gemm_mma<2, true >, cudaFuncAttributeMaxDynamicSharedMemorySize, SM_TOTAL);
    cudaFuncSetAttribute(gemm_mma<2, false>, cudaFuncAttributeMaxDynamicSharedMemorySize, SM_TOTAL);

    // weight conversion (every replay) — 2 merged launches
    convert_w1_kernel<<<dim3(K1PAD / 16, HID_ / 16, 2 * NBLK_), 256>>>(
        s1_W1, s2_W1, w1h[0], w1l[0], w1h[1], w1l[1]);
    convert_w2_kernel<<<dim3(K2PAD / 16, N2PAD / 16, 2 * NBLK_), 256>>>(
        s1_W2, s2_W2, w2h[0], w2l[0], w2h[1], w2l[1]);

    init_kernel<<<(B_ * (K1PAD - HALF_) + 255) / 256, 256>>>(
        perms, jac, xbh, xbl, ysh, ysl, inv);

    // block-0 permute into parity-0 buffers
    permute_kernel<<<(B_ * D_ + 255) / 256, 256>>>(x, perms, pxa, pxb, xbh, xbl);

    const dim3 g1Grid(HID_ / TILE_N,  B_ / TILE_M);   // (8, 32)
    const dim3 g2Grid(N2PAD / TILE_N, B_ / TILE_M);   // (14, 32)

    const size_t W1sz  = (size_t)(HALF_ + CONDN_) * HID_;
    const size_t W1tsz = (size_t)HID_ * K1PAD;
    const size_t W2tsz = (size_t)N2PAD * K2PAD;
    const size_t XAH = (size_t)B_ * HALF_;
    const size_t XBK = (size_t)B_ * K1PAD;

    for (int k = 0; k < NBLK_; k++) {
        const int p = k & 1, q = (k + 1) & 1;
        float* xaP = pxa + (size_t)p * XAH;
        float* xbP = pxb + (size_t)p * XAH;
        __nv_bfloat16* xbhP = xbh + (size_t)p * XBK;
        __nv_bfloat16* xblP = xbl + (size_t)p * XBK;
        float* xaQ = pxa + (size_t)q * XAH;
        float* xbQ = pxb + (size_t)q * XAH;
        __nv_bfloat16* xbhQ = xbh + (size_t)q * XBK;
        __nv_bfloat16* xblQ = xbl + (size_t)q * XBK;
        const int* invp = inv + (size_t)(k + 1) * D_;   // unused for k==19
        const bool last = (k == NBLK_ - 1);

        // ---- subnet s2 hidden ----
        gemm_mma<0, false><<<g1Grid, 256, SM_TOTAL>>>(
            xbhP, xblP, w1h[1] + k * W1tsz, w1l[1] + k * W1tsz, K1PAD, K1PAD / TILE_K,
            s2_b1 + (size_t)k * HID_, s2_W1 + k * W1sz, l,
            nullptr, nullptr, nullptr, hh, hl,
            nullptr, nullptr, nullptr, nullptr, nullptr);
        // ---- subnet s2 output + coupling -> y1 (split natural; scatter or z) ----
        if (!last) {
            gemm_mma<1, true><<<g2Grid, 256, SM_TOTAL>>>(
                hh, hl, w2h[1] + k * W2tsz, w2l[1] + k * W2tsz, K2PAD, K2PAD / TILE_K,
                s2_b2 + (size_t)k * D_, nullptr, nullptr,
                xaP, nullptr, jac, ysh, ysl,
                invp, xaQ, xbQ, xbhQ, xblQ);
        } else {
            gemm_mma<1, false><<<g2Grid, 256, SM_TOTAL>>>(
                hh, hl, w2h[1] + k * W2tsz, w2l[1] + k * W2tsz, K2PAD, K2PAD / TILE_K,
                s2_b2 + (size_t)k * D_, nullptr, nullptr,
                xaP, z, jac, ysh, ysl,
                nullptr, nullptr, nullptr, nullptr, nullptr);
        }

        // ---- subnet s1 hidden ----
        gemm_mma<0, false><<<g1Grid, 256, SM_TOTAL>>>(
            ysh, ysl, w1h[0] + k * W1tsz, w1l[0] + k * W1tsz, K1PAD, K1PAD / TILE_K,
            s1_b1 + (size_t)k * HID_, s1_W1 + k * W1sz, l,
            nullptr, nullptr, nullptr, hh, hl,
            nullptr, nullptr, nullptr, nullptr, nullptr);
        // ---- subnet s1 output + coupling -> y2 (scatter or z) ----
        if (!last) {
            gemm_mma<2, true><<<g2Grid, 256, SM_TOTAL>>>(
                hh, hl, w2h[0] + k * W2tsz, w2l[0] + k * W2tsz, K2PAD, K2PAD / TILE_K,
                s1_b2 + (size_t)k * D_, nullptr, nullptr,
                xbP, nullptr, jac, nullptr, nullptr,
                invp + HALF_, xaQ, xbQ, xbhQ, xblQ);
        } else {
            gemm_mma<2, false><<<g2Grid, 256, SM_TOTAL>>>(
                hh, hl, w2h[0] + k * W2tsz, w2l[0] + k * W2tsz, K2PAD, K2PAD / TILE_K,
                s1_b2 + (size_t)k * D_, nullptr, nullptr,
                xbP, z + HALF_, jac, nullptr, nullptr,
                nullptr, nullptr, nullptr, nullptr, nullptr);
        }
    }
}

// round 7
// speedup vs baseline: 1.3728x; 1.3728x over previous
#include <cuda_runtime.h>
#include <cuda_bf16.h>
#include <cstdint>
#include <math.h>

// Problem constants
#define B_     4096
#define HB_    2048         // rows per stream chain
#define D_     784
#define HALF_  392
#define HID_   512
#define CONDN_ 10
#define NBLK_  20

#define K1PAD  416          // 392 padded to 13*32
#define K2PAD  512
#define N2PAD  832          // 416 (s,t)-pairs * 2

// GEMM tiling: CTA 128(M) x 64(N) x 32(K-stage), 8 warps of 32x32, 2-stage
#define TILE_M 128
#define TILE_N 64
#define TILE_K 32

// smem stage layout (bytes): rows padded 64B->80B for conflict-free ldmatrix
#define SA_ROW   80
#define ST_AHI   0
#define ST_ALO   10240
#define ST_BHI   20480
#define ST_BLO   25600
#define ST_SIZE  30720
#define SM_TOTAL (2 * ST_SIZE)

// ---------------- PTX helpers ----------------
__device__ __forceinline__ uint32_t smem_u32(const void* p) {
    uint32_t a;
    asm("{ .reg .u64 t; cvta.to.shared.u64 t, %1; cvt.u32.u64 %0, t; }" : "=r"(a) : "l"(p));
    return a;
}
#define CP_ASYNC16(dst, src) \
    asm volatile("cp.async.cg.shared.global [%0], [%1], 16;" :: "r"(dst), "l"(src))
#define CP_COMMIT() asm volatile("cp.async.commit_group;" ::: "memory")
#define CP_WAIT1()  asm volatile("cp.async.wait_group 1;" ::: "memory")
#define CP_WAIT0()  asm volatile("cp.async.wait_group 0;" ::: "memory")

__device__ __forceinline__ void ldm4(uint32_t& r0, uint32_t& r1, uint32_t& r2, uint32_t& r3,
                                     uint32_t a) {
    asm volatile("ldmatrix.sync.aligned.m8n8.x4.shared.b16 {%0,%1,%2,%3}, [%4];"
                 : "=r"(r0), "=r"(r1), "=r"(r2), "=r"(r3) : "r"(a));
}
__device__ __forceinline__ void mma_bf16(float& c0, float& c1, float& c2, float& c3,
                                         uint32_t a0, uint32_t a1, uint32_t a2, uint32_t a3,
                                         uint32_t b0, uint32_t b1) {
    asm volatile(
        "mma.sync.aligned.m16n8k16.row.col.f32.bf16.bf16.f32 "
        "{%0,%1,%2,%3}, {%4,%5,%6,%7}, {%8,%9}, {%0,%1,%2,%3};"
        : "+f"(c0), "+f"(c1), "+f"(c2), "+f"(c3)
        : "r"(a0), "r"(a1), "r"(a2), "r"(a3), "r"(b0), "r"(b1));
}

// ---------------- device scratch ----------------
__device__ float g_v [B_ * D_];
__device__ float g_xa[B_ * HALF_];
__device__ float g_xb[B_ * HALF_];

__device__ __nv_bfloat16 g_xbh[B_ * K1PAD];
__device__ __nv_bfloat16 g_xbl[B_ * K1PAD];
__device__ __nv_bfloat16 g_ysh[B_ * K1PAD];
__device__ __nv_bfloat16 g_ysl[B_ * K1PAD];
__device__ __nv_bfloat16 g_hh [B_ * K2PAD];
__device__ __nv_bfloat16 g_hl [B_ * K2PAD];

// transposed + split weights: W1t [blk][512][416], W2t interleaved [blk][832][512]
__device__ __nv_bfloat16 g_s1w1_hi[NBLK_ * HID_ * K1PAD];
__device__ __nv_bfloat16 g_s1w1_lo[NBLK_ * HID_ * K1PAD];
__device__ __nv_bfloat16 g_s2w1_hi[NBLK_ * HID_ * K1PAD];
__device__ __nv_bfloat16 g_s2w1_lo[NBLK_ * HID_ * K1PAD];
__device__ __nv_bfloat16 g_s1w2_hi[NBLK_ * N2PAD * K2PAD];
__device__ __nv_bfloat16 g_s1w2_lo[NBLK_ * N2PAD * K2PAD];
__device__ __nv_bfloat16 g_s2w2_hi[NBLK_ * N2PAD * K2PAD];
__device__ __nv_bfloat16 g_s2w2_lo[NBLK_ * N2PAD * K2PAD];

__device__ __forceinline__ void split1(float v, __nv_bfloat16& h, __nv_bfloat16& l) {
    h = __float2bfloat16_rn(v);
    l = __float2bfloat16_rn(v - __bfloat162float(h));
}

// ---------------- small kernels ----------------
// zero jac + zero K-pad columns of split activation buffers
__global__ void init_kernel(float* __restrict__ jac,
                            __nv_bfloat16* __restrict__ xbh, __nv_bfloat16* __restrict__ xbl,
                            __nv_bfloat16* __restrict__ ysh, __nv_bfloat16* __restrict__ ysl) {
    int idx = blockIdx.x * blockDim.x + threadIdx.x;
    if (idx < B_) jac[idx] = 0.f;
    if (idx < B_ * (K1PAD - HALF_)) {
        int i = idx / (K1PAD - HALF_);
        int jj = HALF_ + idx % (K1PAD - HALF_);
        __nv_bfloat16 zz = __float2bfloat16_rn(0.f);
        size_t o = (size_t)i * K1PAD + jj;
        xbh[o] = zz; xbl[o] = zz; ysh[o] = zz; ysl[o] = zz;
    }
}

// permute + split second half (operates on HB_ rows; pointers pre-offset)
__global__ void permute_kernel(const float* __restrict__ v,
                               const int* __restrict__ perm,
                               float* __restrict__ xa,
                               float* __restrict__ xb,
                               __nv_bfloat16* __restrict__ xbh,
                               __nv_bfloat16* __restrict__ xbl) {
    int idx = blockIdx.x * blockDim.x + threadIdx.x;
    if (idx >= HB_ * D_) return;
    int i = idx / D_;
    int j = idx - i * D_;
    float val = v[(size_t)i * D_ + perm[j]];
    if (j < HALF_) {
        xa[(size_t)i * HALF_ + j] = val;
    } else {
        int jj = j - HALF_;
        xb[(size_t)i * HALF_ + jj] = val;
        __nv_bfloat16 h, l;
        split1(val, h, l);
        xbh[(size_t)i * K1PAD + jj] = h;
        xbl[(size_t)i * K1PAD + jj] = l;
    }
}

// transpose + split W1 (both subnets via grid.z): [blk][402][512] -> [blk][512][416]
__global__ void convert_w1_kernel(const float* __restrict__ Ws1, const float* __restrict__ Ws2,
                                  __nv_bfloat16* __restrict__ hi1, __nv_bfloat16* __restrict__ lo1,
                                  __nv_bfloat16* __restrict__ hi2, __nv_bfloat16* __restrict__ lo2) {
    __shared__ float t[16][17];
    int zz = blockIdx.z;
    int sel = zz >= NBLK_;
    int blk = sel ? zz - NBLK_ : zz;
    const float* W = sel ? Ws2 : Ws1;
    __nv_bfloat16* hi = sel ? hi2 : hi1;
    __nv_bfloat16* lo = sel ? lo2 : lo1;
    int bk = blockIdx.x;
    int bn = blockIdx.y;
    int tx = threadIdx.x & 15, ty = threadIdx.x >> 4;
    int k = bk * 16 + ty, n = bn * 16 + tx;
    float v = (k < HALF_) ? W[((size_t)blk * (HALF_ + CONDN_) + k) * HID_ + n] : 0.f;
    t[ty][tx] = v;
    __syncthreads();
    float o = t[tx][ty];
    __nv_bfloat16 h, l;
    split1(o, h, l);
    size_t oidx = ((size_t)blk * HID_ + bn * 16 + ty) * K1PAD + bk * 16 + tx;
    hi[oidx] = h;
    lo[oidx] = l;
}

// transpose + split + (s,t)-interleave W2: [blk][512][784] -> [blk][832][512]
// output row 2p   = original col p      (s_p)   [p < 392, else 0]
// output row 2p+1 = original col 392+p  (t_p)
__global__ void convert_w2_kernel(const float* __restrict__ Ws1, const float* __restrict__ Ws2,
                                  __nv_bfloat16* __restrict__ hi1, __nv_bfloat16* __restrict__ lo1,
                                  __nv_bfloat16* __restrict__ hi2, __nv_bfloat16* __restrict__ lo2) {
    __shared__ float t[16][17];
    int zz = blockIdx.z;
    int sel = zz >= NBLK_;
    int blk = sel ? zz - NBLK_ : zz;
    const float* W = sel ? Ws2 : Ws1;
    __nv_bfloat16* hi = sel ? hi2 : hi1;
    __nv_bfloat16* lo = sel ? lo2 : lo1;
    int bk = blockIdx.x;
    int bn = blockIdx.y;
    int tx = threadIdx.x & 15, ty = threadIdx.x >> 4;
    int k = bk * 16 + ty;
    int nOut = bn * 16 + tx;
    int p = nOut >> 1;
    int orig = (nOut & 1) ? (HALF_ + p) : p;
    float v = (p < HALF_) ? W[((size_t)blk * HID_ + k) * D_ + orig] : 0.f;
    t[ty][tx] = v;
    __syncthreads();
    float o = t[tx][ty];
    __nv_bfloat16 h, l;
    split1(o, h, l);
    size_t oidx = ((size_t)blk * N2PAD + bn * 16 + ty) * K2PAD + bk * 16 + tx;
    hi[oidx] = h;
    lo[oidx] = l;
}

// ---------------- fused HMMA GEMM ----------------
// MODE 0: hidden layer. C = relu(A@Bt^T + bias + Wcond[392+lab[m]]), write split bf16.
// MODE 1/2: output layer, interleaved (s,t) columns, fused coupling:
//   p = n/2; s = acc(n)+bias[p]; t = acc(n+1)+bias[392+p];
//   ls = 0.636*atan(s); y = exp(ls)*xo[m][p] + t; Yf[m*D_+p] = y; jac[m] += ls;
//   MODE 1 additionally writes split bf16 y (Chi/Clo stride K1PAD).
template<int MODE>
__global__ __launch_bounds__(256, 2)
void gemm_mma(const __nv_bfloat16* __restrict__ Ahi, const __nv_bfloat16* __restrict__ Alo,
              const __nv_bfloat16* __restrict__ Bhi, const __nv_bfloat16* __restrict__ Blo,
              int Ka, int nch,
              const float* __restrict__ bias,
              const float* __restrict__ Wcond, const int* __restrict__ lab,
              const float* __restrict__ xo,
              float* __restrict__ Yf, float* __restrict__ jac,
              __nv_bfloat16* __restrict__ Chi, __nv_bfloat16* __restrict__ Clo) {
    extern __shared__ __align__(128) char sm[];
    const int tid = threadIdx.x;
    const int lane = tid & 31, wid = tid >> 5;
    const int wm = wid & 3, wn = wid >> 2;           // 4x2 warp grid, 32x32 warp tiles
    const int m0 = blockIdx.y * TILE_M, n0 = blockIdx.x * TILE_N;
    const uint32_t sb = smem_u32(sm);

    const int a_row = tid >> 2, a_seg = tid & 3;
    const int b_row = tid >> 2, b_seg = tid & 3;

    float acc[2][4][4];
#pragma unroll
    for (int i = 0; i < 2; i++)
#pragma unroll
        for (int j = 0; j < 4; j++)
#pragma unroll
            for (int q = 0; q < 4; q++) acc[i][j][q] = 0.f;

#define LOAD_STAGE(c, s)                                                                  \
    do {                                                                                  \
        uint32_t st = sb + (s) * ST_SIZE;                                                 \
        const __nv_bfloat16* a0s = Ahi + (size_t)(m0 + a_row) * Ka + (c) * 32 + a_seg * 8;\
        const __nv_bfloat16* a1s = a0s + (size_t)64 * Ka;                                 \
        const __nv_bfloat16* a2s = Alo + (size_t)(m0 + a_row) * Ka + (c) * 32 + a_seg * 8;\
        const __nv_bfloat16* a3s = a2s + (size_t)64 * Ka;                                 \
        CP_ASYNC16(st + ST_AHI + a_row * SA_ROW + a_seg * 16, a0s);                       \
        CP_ASYNC16(st + ST_AHI + (a_row + 64) * SA_ROW + a_seg * 16, a1s);                \
        CP_ASYNC16(st + ST_ALO + a_row * SA_ROW + a_seg * 16, a2s);                       \
        CP_ASYNC16(st + ST_ALO + (a_row + 64) * SA_ROW + a_seg * 16, a3s);                \
        CP_ASYNC16(st + ST_BHI + b_row * SA_ROW + b_seg * 16,                             \
                   Bhi + (size_t)(n0 + b_row) * Ka + (c) * 32 + b_seg * 8);               \
        CP_ASYNC16(st + ST_BLO + b_row * SA_ROW + b_seg * 16,                             \
                   Blo + (size_t)(n0 + b_row) * Ka + (c) * 32 + b_seg * 8);               \
    } while (0)

    LOAD_STAGE(0, 0);
    CP_COMMIT();

    const uint32_t a_lrow = (lane & 15);
    const uint32_t a_lcol = (lane >> 4) << 4;
    const uint32_t b_lrow = (lane & 7) + ((lane & 16) >> 1);
    const uint32_t b_lcol = (lane & 8) << 1;

    for (int c = 0; c < nch; c++) {
        if (c + 1 < nch) {
            LOAD_STAGE(c + 1, (c + 1) & 1);
            CP_COMMIT();
            CP_WAIT1();
        } else {
            CP_WAIT0();
        }
        __syncthreads();

        uint32_t st = sb + (c & 1) * ST_SIZE;
#pragma unroll
        for (int s = 0; s < 2; s++) {
            uint32_t a[2][2][4];
            uint32_t b[2][4][2];
#pragma unroll
            for (int hl = 0; hl < 2; hl++) {
#pragma unroll
                for (int mm = 0; mm < 2; mm++) {
                    uint32_t ad = st + (hl ? ST_ALO : ST_AHI)
                                + (wm * 32 + mm * 16 + a_lrow) * SA_ROW + a_lcol + s * 32;
                    ldm4(a[hl][mm][0], a[hl][mm][1], a[hl][mm][2], a[hl][mm][3], ad);
                }
#pragma unroll
                for (int nt = 0; nt < 2; nt++) {
                    uint32_t bd = st + (hl ? ST_BLO : ST_BHI)
                                + (wn * 32 + nt * 16 + b_lrow) * SA_ROW + b_lcol + s * 32;
                    ldm4(b[hl][2 * nt][0], b[hl][2 * nt][1],
                         b[hl][2 * nt + 1][0], b[hl][2 * nt + 1][1], bd);
                }
            }
#pragma unroll
            for (int mm = 0; mm < 2; mm++) {
#pragma unroll
                for (int nn = 0; nn < 4; nn++) {
                    float* cc = acc[mm][nn];
                    mma_bf16(cc[0], cc[1], cc[2], cc[3],
                             a[0][mm][0], a[0][mm][1], a[0][mm][2], a[0][mm][3],
                             b[0][nn][0], b[0][nn][1]);
                    mma_bf16(cc[0], cc[1], cc[2], cc[3],
                             a[0][mm][0], a[0][mm][1], a[0][mm][2], a[0][mm][3],
                             b[1][nn][0], b[1][nn][1]);
                    mma_bf16(cc[0], cc[1], cc[2], cc[3],
                             a[1][mm][0], a[1][mm][1], a[1][mm][2], a[1][mm][3],
                             b[0][nn][0], b[0][nn][1]);
                }
            }
        }
        __syncthreads();
    }
#undef LOAD_STAGE

    // ---- epilogue ----
    const int rbase = lane >> 2;
    const int cbase = (lane & 3) * 2;

    if (MODE == 0) {
#pragma unroll
        for (int mm = 0; mm < 2; mm++) {
#pragma unroll
            for (int h = 0; h < 2; h++) {
                int m = m0 + wm * 32 + mm * 16 + rbase + h * 8;
                const float* wc = Wcond + (size_t)(HALF_ + lab[m]) * HID_;
#pragma unroll
                for (int nn = 0; nn < 4; nn++) {
                    int n = n0 + wn * 32 + nn * 8 + cbase;
                    float v0 = acc[mm][nn][h * 2 + 0] + bias[n] + wc[n];
                    float v1 = acc[mm][nn][h * 2 + 1] + bias[n + 1] + wc[n + 1];
                    v0 = fmaxf(v0, 0.f);
                    v1 = fmaxf(v1, 0.f);
                    __nv_bfloat16 h0, l0, h1, l1;
                    split1(v0, h0, l0);
                    split1(v1, h1, l1);
                    __nv_bfloat162 hp; hp.x = h0; hp.y = h1;
                    __nv_bfloat162 lp; lp.x = l0; lp.y = l1;
                    *reinterpret_cast<__nv_bfloat162*>(Chi + (size_t)m * HID_ + n) = hp;
                    *reinterpret_cast<__nv_bfloat162*>(Clo + (size_t)m * HID_ + n) = lp;
                }
            }
        }
    } else {
#pragma unroll
        for (int mm = 0; mm < 2; mm++) {
#pragma unroll
            for (int h = 0; h < 2; h++) {
                int m = m0 + wm * 32 + mm * 16 + rbase + h * 8;
                float jl = 0.f;
#pragma unroll
                for (int nn = 0; nn < 4; nn++) {
                    int n = n0 + wn * 32 + nn * 8 + cbase;   // always even
                    int p = n >> 1;
                    if (p < HALF_) {
                        float s = acc[mm][nn][h * 2 + 0] + bias[p];
                        float t = acc[mm][nn][h * 2 + 1] + bias[HALF_ + p];
                        float ls = 0.636f * atanf(s);
                        float y = expf(ls) * xo[(size_t)m * HALF_ + p] + t;
                        Yf[(size_t)m * D_ + p] = y;
                        if (MODE == 1) {
                            __nv_bfloat16 yhh, yll;
                            split1(y, yhh, yll);
                            Chi[(size_t)m * K1PAD + p] = yhh;
                            Clo[(size_t)m * K1PAD + p] = yll;
                        }
                        jl += ls;
                    }
                }
                jl += __shfl_xor_sync(0xffffffffu, jl, 1);
                jl += __shfl_xor_sync(0xffffffffu, jl, 2);
                if ((lane & 3) == 0) atomicAdd(&jac[m], jl);
            }
        }
    }
}

// ---------------- host launcher ----------------
extern "C" void kernel_launch(void* const* d_in, const int* in_sizes, int n_in,
                              void* d_out, int out_size) {
    const float* x     = (const float*)d_in[0];
    const int*   l     = (const int*)  d_in[1];
    const int*   perms = (const int*)  d_in[2];
    const float* s1_W1 = (const float*)d_in[3];
    const float* s1_b1 = (const float*)d_in[4];
    const float* s1_W2 = (const float*)d_in[5];
    const float* s1_b2 = (const float*)d_in[6];
    const float* s2_W1 = (const float*)d_in[7];
    const float* s2_b1 = (const float*)d_in[8];
    const float* s2_W2 = (const float*)d_in[9];
    const float* s2_b2 = (const float*)d_in[10];

    float* z   = (float*)d_out;
    float* jac = z + (size_t)B_ * D_;

    float *pv, *pxa, *pxb;
    cudaGetSymbolAddress((void**)&pv,  g_v);
    cudaGetSymbolAddress((void**)&pxa, g_xa);
    cudaGetSymbolAddress((void**)&pxb, g_xb);

    __nv_bfloat16 *xbh, *xbl, *ysh, *ysl, *hh, *hl;
    cudaGetSymbolAddress((void**)&xbh, g_xbh);
    cudaGetSymbolAddress((void**)&xbl, g_xbl);
    cudaGetSymbolAddress((void**)&ysh, g_ysh);
    cudaGetSymbolAddress((void**)&ysl, g_ysl);
    cudaGetSymbolAddress((void**)&hh,  g_hh);
    cudaGetSymbolAddress((void**)&hl,  g_hl);

    __nv_bfloat16 *w1h[2], *w1l[2], *w2h[2], *w2l[2];
    cudaGetSymbolAddress((void**)&w1h[0], g_s1w1_hi);
    cudaGetSymbolAddress((void**)&w1l[0], g_s1w1_lo);
    cudaGetSymbolAddress((void**)&w1h[1], g_s2w1_hi);
    cudaGetSymbolAddress((void**)&w1l[1], g_s2w1_lo);
    cudaGetSymbolAddress((void**)&w2h[0], g_s1w2_hi);
    cudaGetSymbolAddress((void**)&w2l[0], g_s1w2_lo);
    cudaGetSymbolAddress((void**)&w2h[1], g_s2w2_hi);
    cudaGetSymbolAddress((void**)&w2l[1], g_s2w2_lo);

    cudaFuncSetAttribute(gemm_mma<0>, cudaFuncAttributeMaxDynamicSharedMemorySize, SM_TOTAL);
    cudaFuncSetAttribute(gemm_mma<1>, cudaFuncAttributeMaxDynamicSharedMemorySize, SM_TOTAL);
    cudaFuncSetAttribute(gemm_mma<2>, cudaFuncAttributeMaxDynamicSharedMemorySize, SM_TOTAL);

    // persistent streams/events for fork-join (created once; deterministic work per call)
    static cudaStream_t st[2];
    static cudaEvent_t evFork, evJ0, evJ1;
    static bool inited = false;
    if (!inited) {
        cudaStreamCreateWithFlags(&st[0], cudaStreamNonBlocking);
        cudaStreamCreateWithFlags(&st[1], cudaStreamNonBlocking);
        cudaEventCreateWithFlags(&evFork, cudaEventDisableTiming);
        cudaEventCreateWithFlags(&evJ0,   cudaEventDisableTiming);
        cudaEventCreateWithFlags(&evJ1,   cudaEventDisableTiming);
        inited = true;
    }

    // ---- shared prologue on origin stream ----
    convert_w1_kernel<<<dim3(K1PAD / 16, HID_ / 16, 2 * NBLK_), 256>>>(
        s1_W1, s2_W1, w1h[0], w1l[0], w1h[1], w1l[1]);
    convert_w2_kernel<<<dim3(K2PAD / 16, N2PAD / 16, 2 * NBLK_), 256>>>(
        s1_W2, s2_W2, w2h[0], w2l[0], w2h[1], w2l[1]);
    init_kernel<<<(B_ * (K1PAD - HALF_) + 255) / 256, 256>>>(jac, xbh, xbl, ysh, ysl);

    // ---- fork ----
    cudaEventRecord(evFork, 0);
    cudaStreamWaitEvent(st[0], evFork, 0);
    cudaStreamWaitEvent(st[1], evFork, 0);

    const dim3 g1Grid(HID_ / TILE_N,  HB_ / TILE_M);   // (8, 16)
    const dim3 g2Grid(N2PAD / TILE_N, HB_ / TILE_M);   // (13, 16)
    const int permGrid = (HB_ * D_ + 255) / 256;

    const size_t W1sz  = (size_t)(HALF_ + CONDN_) * HID_;
    const size_t W1tsz = (size_t)HID_ * K1PAD;
    const size_t W2tsz = (size_t)N2PAD * K2PAD;

    for (int half = 0; half < 2; half++) {
        cudaStream_t s = st[half];
        const size_t off = (size_t)half * HB_;
        const float* xH  = x   + off * D_;
        float* pvH       = pv  + off * D_;
        float* zH        = z   + off * D_;
        float* jacH      = jac + off;
        const int* lH    = l   + off;
        float* xaH = pxa + off * HALF_;
        float* xbH = pxb + off * HALF_;
        __nv_bfloat16* xbhH = xbh + off * K1PAD;
        __nv_bfloat16* xblH = xbl + off * K1PAD;
        __nv_bfloat16* yshH = ysh + off * K1PAD;
        __nv_bfloat16* yslH = ysl + off * K1PAD;
        __nv_bfloat16* hhH  = hh  + off * K2PAD;
        __nv_bfloat16* hlH  = hl  + off * K2PAD;

        for (int k = 0; k < NBLK_; k++) {
            const float* vsrc = (k == 0) ? xH : pvH;
            float* vdst = (k == NBLK_ - 1) ? zH : pvH;

            permute_kernel<<<permGrid, 256, 0, s>>>(
                vsrc, perms + (size_t)k * D_, xaH, xbH, xbhH, xblH);

            // subnet s2: hidden, then output+coupling -> y1 (fp32 vdst + split)
            gemm_mma<0><<<g1Grid, 256, SM_TOTAL, s>>>(
                xbhH, xblH, w1h[1] + k * W1tsz, w1l[1] + k * W1tsz, K1PAD, K1PAD / TILE_K,
                s2_b1 + (size_t)k * HID_, s2_W1 + k * W1sz, lH,
                nullptr, nullptr, nullptr, hhH, hlH);
            gemm_mma<1><<<g2Grid, 256, SM_TOTAL, s>>>(
                hhH, hlH, w2h[1] + k * W2tsz, w2l[1] + k * W2tsz, K2PAD, K2PAD / TILE_K,
                s2_b2 + (size_t)k * D_, nullptr, nullptr,
                xaH, vdst, jacH, yshH, yslH);

            // subnet s1: hidden, then output+coupling -> y2 (fp32 vdst+HALF_)
            gemm_mma<0><<<g1Grid, 256, SM_TOTAL, s>>>(
                yshH, yslH, w1h[0] + k * W1tsz, w1l[0] + k * W1tsz, K1PAD, K1PAD / TILE_K,
                s1_b1 + (size_t)k * HID_, s1_W1 + k * W1sz, lH,
                nullptr, nullptr, nullptr, hhH, hlH);
            gemm_mma<2><<<g2Grid, 256, SM_TOTAL, s>>>(
                hhH, hlH, w2h[0] + k * W2tsz, w2l[0] + k * W2tsz, K2PAD, K2PAD / TILE_K,
                s1_b2 + (size_t)k * D_, nullptr, nullptr,
                xbH, vdst + HALF_, jacH, nullptr, nullptr);
        }
    }

    // ---- join ----
    cudaEventRecord(evJ0, st[0]);
    cudaEventRecord(evJ1, st[1]);
    cudaStreamWaitEvent(0, evJ0, 0);
    cudaStreamWaitEvent(0, evJ1, 0);
}

// round 9
// speedup vs baseline: 1.3898x; 1.0124x over previous
#include <cuda_runtime.h>
#include <cuda_bf16.h>
#include <cstdint>
#include <math.h>

// Problem constants
#define B_     4096
#define HB_    2048         // rows per stream chain
#define D_     784
#define HALF_  392
#define HID_   512
#define CONDN_ 10
#define NBLK_  20

#define K1PAD  416          // 392 padded to 13*32
#define K2PAD  512
#define N2PAD  832          // 416 (s,t)-pairs * 2

// GEMM tiling: CTA 128(M) x 64(N) x 32(K-stage), 8 warps of 32x32, 3-stage pipeline
#define TILE_M 128
#define TILE_N 64
#define TILE_K 32
#define STAGES 3

// smem stage layout (bytes): rows padded 64B->80B for conflict-free ldmatrix
#define SA_ROW   80
#define ST_AHI   0
#define ST_ALO   10240
#define ST_BHI   20480
#define ST_BLO   25600
#define ST_SIZE  30720
#define SM_TOTAL (STAGES * ST_SIZE)

// ---------------- PTX helpers ----------------
__device__ __forceinline__ uint32_t smem_u32(const void* p) {
    uint32_t a;
    asm("{ .reg .u64 t; cvta.to.shared.u64 t, %1; cvt.u32.u64 %0, t; }" : "=r"(a) : "l"(p));
    return a;
}
#define CP_ASYNC16(dst, src) \
    asm volatile("cp.async.cg.shared.global [%0], [%1], 16;" :: "r"(dst), "l"(src))
#define CP_COMMIT() asm volatile("cp.async.commit_group;" ::: "memory")
#define CP_WAIT1()  asm volatile("cp.async.wait_group 1;" ::: "memory")

__device__ __forceinline__ void ldm4(uint32_t& r0, uint32_t& r1, uint32_t& r2, uint32_t& r3,
                                     uint32_t a) {
    asm volatile("ldmatrix.sync.aligned.m8n8.x4.shared.b16 {%0,%1,%2,%3}, [%4];"
                 : "=r"(r0), "=r"(r1), "=r"(r2), "=r"(r3) : "r"(a));
}
__device__ __forceinline__ void mma_bf16(float& c0, float& c1, float& c2, float& c3,
                                         uint32_t a0, uint32_t a1, uint32_t a2, uint32_t a3,
                                         uint32_t b0, uint32_t b1) {
    asm volatile(
        "mma.sync.aligned.m16n8k16.row.col.f32.bf16.bf16.f32 "
        "{%0,%1,%2,%3}, {%4,%5,%6,%7}, {%8,%9}, {%0,%1,%2,%3};"
        : "+f"(c0), "+f"(c1), "+f"(c2), "+f"(c3)
        : "r"(a0), "r"(a1), "r"(a2), "r"(a3), "r"(b0), "r"(b1));
}

// ---------------- device scratch ----------------
__device__ float g_v [B_ * D_];
__device__ float g_xa[B_ * HALF_];
__device__ float g_xb[B_ * HALF_];

__device__ __nv_bfloat16 g_xbh[B_ * K1PAD];
__device__ __nv_bfloat16 g_xbl[B_ * K1PAD];
__device__ __nv_bfloat16 g_ysh[B_ * K1PAD];
__device__ __nv_bfloat16 g_ysl[B_ * K1PAD];
__device__ __nv_bfloat16 g_hh [B_ * K2PAD];
__device__ __nv_bfloat16 g_hl [B_ * K2PAD];

// transposed + split weights: W1t [blk][512][416], W2t interleaved [blk][832][512]
__device__ __nv_bfloat16 g_s1w1_hi[NBLK_ * HID_ * K1PAD];
__device__ __nv_bfloat16 g_s1w1_lo[NBLK_ * HID_ * K1PAD];
__device__ __nv_bfloat16 g_s2w1_hi[NBLK_ * HID_ * K1PAD];
__device__ __nv_bfloat16 g_s2w1_lo[NBLK_ * HID_ * K1PAD];
__device__ __nv_bfloat16 g_s1w2_hi[NBLK_ * N2PAD * K2PAD];
__device__ __nv_bfloat16 g_s1w2_lo[NBLK_ * N2PAD * K2PAD];
__device__ __nv_bfloat16 g_s2w2_hi[NBLK_ * N2PAD * K2PAD];
__device__ __nv_bfloat16 g_s2w2_lo[NBLK_ * N2PAD * K2PAD];

__device__ __forceinline__ void split1(float v, __nv_bfloat16& h, __nv_bfloat16& l) {
    h = __float2bfloat16_rn(v);
    l = __float2bfloat16_rn(v - __bfloat162float(h));
}

// ---------------- small kernels ----------------
// zero jac + zero K-pad columns of split activation buffers
__global__ void init_kernel(float* __restrict__ jac,
                            __nv_bfloat16* __restrict__ xbh, __nv_bfloat16* __restrict__ xbl,
                            __nv_bfloat16* __restrict__ ysh, __nv_bfloat16* __restrict__ ysl) {
    int idx = blockIdx.x * blockDim.x + threadIdx.x;
    if (idx < B_) jac[idx] = 0.f;
    if (idx < B_ * (K1PAD - HALF_)) {
        int i = idx / (K1PAD - HALF_);
        int jj = HALF_ + idx % (K1PAD - HALF_);
        __nv_bfloat16 zz = __float2bfloat16_rn(0.f);
        size_t o = (size_t)i * K1PAD + jj;
        xbh[o] = zz; xbl[o] = zz; ysh[o] = zz; ysl[o] = zz;
    }
}

// permute + split second half (operates on HB_ rows; pointers pre-offset)
__global__ void permute_kernel(const float* __restrict__ v,
                               const int* __restrict__ perm,
                               float* __restrict__ xa,
                               float* __restrict__ xb,
                               __nv_bfloat16* __restrict__ xbh,
                               __nv_bfloat16* __restrict__ xbl) {
    int idx = blockIdx.x * blockDim.x + threadIdx.x;
    if (idx >= HB_ * D_) return;
    int i = idx / D_;
    int j = idx - i * D_;
    float val = v[(size_t)i * D_ + perm[j]];
    if (j < HALF_) {
        xa[(size_t)i * HALF_ + j] = val;
    } else {
        int jj = j - HALF_;
        xb[(size_t)i * HALF_ + jj] = val;
        __nv_bfloat16 h, l;
        split1(val, h, l);
        xbh[(size_t)i * K1PAD + jj] = h;
        xbl[(size_t)i * K1PAD + jj] = l;
    }
}

// transpose + split W1 (both subnets via grid.z): [blk][402][512] -> [blk][512][416]
__global__ void convert_w1_kernel(const float* __restrict__ Ws1, const float* __restrict__ Ws2,
                                  __nv_bfloat16* __restrict__ hi1, __nv_bfloat16* __restrict__ lo1,
                                  __nv_bfloat16* __restrict__ hi2, __nv_bfloat16* __restrict__ lo2) {
    __shared__ float t[16][17];
    int zz = blockIdx.z;
    int sel = zz >= NBLK_;
    int blk = sel ? zz - NBLK_ : zz;
    const float* W = sel ? Ws2 : Ws1;
    __nv_bfloat16* hi = sel ? hi2 : hi1;
    __nv_bfloat16* lo = sel ? lo2 : lo1;
    int bk = blockIdx.x;
    int bn = blockIdx.y;
    int tx = threadIdx.x & 15, ty = threadIdx.x >> 4;
    int k = bk * 16 + ty, n = bn * 16 + tx;
    float v = (k < HALF_) ? W[((size_t)blk * (HALF_ + CONDN_) + k) * HID_ + n] : 0.f;
    t[ty][tx] = v;
    __syncthreads();
    float o = t[tx][ty];
    __nv_bfloat16 h, l;
    split1(o, h, l);
    size_t oidx = ((size_t)blk * HID_ + bn * 16 + ty) * K1PAD + bk * 16 + tx;
    hi[oidx] = h;
    lo[oidx] = l;
}

// transpose + split + (s,t)-interleave W2: [blk][512][784] -> [blk][832][512]
__global__ void convert_w2_kernel(const float* __restrict__ Ws1, const float* __restrict__ Ws2,
                                  __nv_bfloat16* __restrict__ hi1, __nv_bfloat16* __restrict__ lo1,
                                  __nv_bfloat16* __restrict__ hi2, __nv_bfloat16* __restrict__ lo2) {
    __shared__ float t[16][17];
    int zz = blockIdx.z;
    int sel = zz >= NBLK_;
    int blk = sel ? zz - NBLK_ : zz;
    const float* W = sel ? Ws2 : Ws1;
    __nv_bfloat16* hi = sel ? hi2 : hi1;
    __nv_bfloat16* lo = sel ? lo2 : lo1;
    int bk = blockIdx.x;
    int bn = blockIdx.y;
    int tx = threadIdx.x & 15, ty = threadIdx.x >> 4;
    int k = bk * 16 + ty;
    int nOut = bn * 16 + tx;
    int p = nOut >> 1;
    int orig = (nOut & 1) ? (HALF_ + p) : p;
    float v = (p < HALF_) ? W[((size_t)blk * HID_ + k) * D_ + orig] : 0.f;
    t[ty][tx] = v;
    __syncthreads();
    float o = t[tx][ty];
    __nv_bfloat16 h, l;
    split1(o, h, l);
    size_t oidx = ((size_t)blk * N2PAD + bn * 16 + ty) * K2PAD + bk * 16 + tx;
    hi[oidx] = h;
    lo[oidx] = l;
}

// ---------------- fused HMMA GEMM (3-stage pipeline, 1 sync/chunk) ----------------
// MODE 0: hidden layer. C = relu(A@Bt^T + bias + Wcond[392+lab[m]]), write split bf16.
// MODE 1/2: output layer, interleaved (s,t) columns, fused coupling:
//   p = n/2; s = acc(n)+bias[p]; t = acc(n+1)+bias[392+p];
//   ls = 0.636*atan(s); y = exp(ls)*xo[m][p] + t; Yf[m*D_+p] = y; jac[m] += ls;
//   MODE 1 additionally writes split bf16 y (Chi/Clo stride K1PAD).
template<int MODE>
__global__ __launch_bounds__(256, 2)
void gemm_mma(const __nv_bfloat16* __restrict__ Ahi, const __nv_bfloat16* __restrict__ Alo,
              const __nv_bfloat16* __restrict__ Bhi, const __nv_bfloat16* __restrict__ Blo,
              int Ka, int nch,
              const float* __restrict__ bias,
              const float* __restrict__ Wcond, const int* __restrict__ lab,
              const float* __restrict__ xo,
              float* __restrict__ Yf, float* __restrict__ jac,
              __nv_bfloat16* __restrict__ Chi, __nv_bfloat16* __restrict__ Clo) {
    extern __shared__ __align__(128) char sm[];
    const int tid = threadIdx.x;
    const int lane = tid & 31, wid = tid >> 5;
    const int wm = wid & 3, wn = wid >> 2;           // 4x2 warp grid, 32x32 warp tiles
    const int m0 = blockIdx.y * TILE_M, n0 = blockIdx.x * TILE_N;
    const uint32_t sb = smem_u32(sm);

    const int a_row = tid >> 2, a_seg = tid & 3;
    const int b_row = tid >> 2, b_seg = tid & 3;

    float acc[2][4][4];
#pragma unroll
    for (int i = 0; i < 2; i++)
#pragma unroll
        for (int j = 0; j < 4; j++)
#pragma unroll
            for (int q = 0; q < 4; q++) acc[i][j][q] = 0.f;

#define LOAD_STAGE(c, s)                                                                  \
    do {                                                                                  \
        uint32_t st = sb + (s) * ST_SIZE;                                                 \
        const __nv_bfloat16* a0s = Ahi + (size_t)(m0 + a_row) * Ka + (c) * 32 + a_seg * 8;\
        const __nv_bfloat16* a1s = a0s + (size_t)64 * Ka;                                 \
        const __nv_bfloat16* a2s = Alo + (size_t)(m0 + a_row) * Ka + (c) * 32 + a_seg * 8;\
        const __nv_bfloat16* a3s = a2s + (size_t)64 * Ka;                                 \
        CP_ASYNC16(st + ST_AHI + a_row * SA_ROW + a_seg * 16, a0s);                       \
        CP_ASYNC16(st + ST_AHI + (a_row + 64) * SA_ROW + a_seg * 16, a1s);                \
        CP_ASYNC16(st + ST_ALO + a_row * SA_ROW + a_seg * 16, a2s);                       \
        CP_ASYNC16(st + ST_ALO + (a_row + 64) * SA_ROW + a_seg * 16, a3s);                \
        CP_ASYNC16(st + ST_BHI + b_row * SA_ROW + b_seg * 16,                             \
                   Bhi + (size_t)(n0 + b_row) * Ka + (c) * 32 + b_seg * 8);               \
        CP_ASYNC16(st + ST_BLO + b_row * SA_ROW + b_seg * 16,                             \
                   Blo + (size_t)(n0 + b_row) * Ka + (c) * 32 + b_seg * 8);               \
    } while (0)

    LOAD_STAGE(0, 0);
    CP_COMMIT();
    LOAD_STAGE(1, 1);
    CP_COMMIT();

    const uint32_t a_lrow = (lane & 15);
    const uint32_t a_lcol = (lane >> 4) << 4;
    const uint32_t b_lrow = (lane & 7) + ((lane & 16) >> 1);
    const uint32_t b_lcol = (lane & 8) << 1;

    int cs = 0, ls2 = 2;
    for (int c = 0; c < nch; c++) {
        CP_WAIT1();            // in-order retirement: stage c resident
        __syncthreads();       // all warps done with stage (c-1)%3; safe to overwrite
        if (c + 2 < nch) LOAD_STAGE(c + 2, ls2);
        CP_COMMIT();           // commit (possibly empty) keeps group count in sync

        uint32_t st = sb + cs * ST_SIZE;
#pragma unroll
        for (int s = 0; s < 2; s++) {
            uint32_t a[2][2][4];
            uint32_t b[2][4][2];
#pragma unroll
            for (int hl = 0; hl < 2; hl++) {
#pragma unroll
                for (int mm = 0; mm < 2; mm++) {
                    uint32_t ad = st + (hl ? ST_ALO : ST_AHI)
                                + (wm * 32 + mm * 16 + a_lrow) * SA_ROW + a_lcol + s * 32;
                    ldm4(a[hl][mm][0], a[hl][mm][1], a[hl][mm][2], a[hl][mm][3], ad);
                }
#pragma unroll
                for (int nt = 0; nt < 2; nt++) {
                    uint32_t bd = st + (hl ? ST_BLO : ST_BHI)
                                + (wn * 32 + nt * 16 + b_lrow) * SA_ROW + b_lcol + s * 32;
                    ldm4(b[hl][2 * nt][0], b[hl][2 * nt][1],
                         b[hl][2 * nt + 1][0], b[hl][2 * nt + 1][1], bd);
                }
            }
#pragma unroll
            for (int mm = 0; mm < 2; mm++) {
#pragma unroll
                for (int nn = 0; nn < 4; nn++) {
                    float* cc = acc[mm][nn];
                    mma_bf16(cc[0], cc[1], cc[2], cc[3],
                             a[0][mm][0], a[0][mm][1], a[0][mm][2], a[0][mm][3],
                             b[0][nn][0], b[0][nn][1]);
                    mma_bf16(cc[0], cc[1], cc[2], cc[3],
                             a[0][mm][0], a[0][mm][1], a[0][mm][2], a[0][mm][3],
                             b[1][nn][0], b[1][nn][1]);
                    mma_bf16(cc[0], cc[1], cc[2], cc[3],
                             a[1][mm][0], a[1][mm][1], a[1][mm][2], a[1][mm][3],
                             b[0][nn][0], b[0][nn][1]);
                }
            }
        }
        cs = (cs == STAGES - 1) ? 0 : cs + 1;
        ls2 = (ls2 == STAGES - 1) ? 0 : ls2 + 1;
    }
#undef LOAD_STAGE

    // ---- epilogue ----
    const int rbase = lane >> 2;
    const int cbase = (lane & 3) * 2;

    if (MODE == 0) {
#pragma unroll
        for (int mm = 0; mm < 2; mm++) {
#pragma unroll
            for (int h = 0; h < 2; h++) {
                int m = m0 + wm * 32 + mm * 16 + rbase + h * 8;
                const float* wc = Wcond + (size_t)(HALF_ + lab[m]) * HID_;
#pragma unroll
                for (int nn = 0; nn < 4; nn++) {
                    int n = n0 + wn * 32 + nn * 8 + cbase;
                    float v0 = acc[mm][nn][h * 2 + 0] + bias[n] + wc[n];
                    float v1 = acc[mm][nn][h * 2 + 1] + bias[n + 1] + wc[n + 1];
                    v0 = fmaxf(v0, 0.f);
                    v1 = fmaxf(v1, 0.f);
                    __nv_bfloat16 h0, l0, h1, l1;
                    split1(v0, h0, l0);
                    split1(v1, h1, l1);
                    __nv_bfloat162 hp; hp.x = h0; hp.y = h1;
                    __nv_bfloat162 lp; lp.x = l0; lp.y = l1;
                    *reinterpret_cast<__nv_bfloat162*>(Chi + (size_t)m * HID_ + n) = hp;
                    *reinterpret_cast<__nv_bfloat162*>(Clo + (size_t)m * HID_ + n) = lp;
                }
            }
        }
    } else {
#pragma unroll
        for (int mm = 0; mm < 2; mm++) {
#pragma unroll
            for (int h = 0; h < 2; h++) {
                int m = m0 + wm * 32 + mm * 16 + rbase + h * 8;
                float jl = 0.f;
#pragma unroll
                for (int nn = 0; nn < 4; nn++) {
                    int n = n0 + wn * 32 + nn * 8 + cbase;   // always even
                    int p = n >> 1;
                    if (p < HALF_) {
                        float s = acc[mm][nn][h * 2 + 0] + bias[p];
                        float t = acc[mm][nn][h * 2 + 1] + bias[HALF_ + p];
                        float ls = 0.636f * atanf(s);
                        float y = expf(ls) * xo[(size_t)m * HALF_ + p] + t;
                        Yf[(size_t)m * D_ + p] = y;
                        if (MODE == 1) {
                            __nv_bfloat16 yhh, yll;
                            split1(y, yhh, yll);
                            Chi[(size_t)m * K1PAD + p] = yhh;
                            Clo[(size_t)m * K1PAD + p] = yll;
                        }
                        jl += ls;
                    }
                }
                jl += __shfl_xor_sync(0xffffffffu, jl, 1);
                jl += __shfl_xor_sync(0xffffffffu, jl, 2);
                if ((lane & 3) == 0) atomicAdd(&jac[m], jl);
            }
        }
    }
}

// ---------------- host launcher ----------------
extern "C" void kernel_launch(void* const* d_in, const int* in_sizes, int n_in,
                              void* d_out, int out_size) {
    const float* x     = (const float*)d_in[0];
    const int*   l     = (const int*)  d_in[1];
    const int*   perms = (const int*)  d_in[2];
    const float* s1_W1 = (const float*)d_in[3];
    const float* s1_b1 = (const float*)d_in[4];
    const float* s1_W2 = (const float*)d_in[5];
    const float* s1_b2 = (const float*)d_in[6];
    const float* s2_W1 = (const float*)d_in[7];
    const float* s2_b1 = (const float*)d_in[8];
    const float* s2_W2 = (const float*)d_in[9];
    const float* s2_b2 = (const float*)d_in[10];

    float* z   = (float*)d_out;
    float* jac = z + (size_t)B_ * D_;

    float *pv, *pxa, *pxb;
    cudaGetSymbolAddress((void**)&pv,  g_v);
    cudaGetSymbolAddress((void**)&pxa, g_xa);
    cudaGetSymbolAddress((void**)&pxb, g_xb);

    __nv_bfloat16 *xbh, *xbl, *ysh, *ysl, *hh, *hl;
    cudaGetSymbolAddress((void**)&xbh, g_xbh);
    cudaGetSymbolAddress((void**)&xbl, g_xbl);
    cudaGetSymbolAddress((void**)&ysh, g_ysh);
    cudaGetSymbolAddress((void**)&ysl, g_ysl);
    cudaGetSymbolAddress((void**)&hh,  g_hh);
    cudaGetSymbolAddress((void**)&hl,  g_hl);

    __nv_bfloat16 *w1h[2], *w1l[2], *w2h[2], *w2l[2];
    cudaGetSymbolAddress((void**)&w1h[0], g_s1w1_hi);
    cudaGetSymbolAddress((void**)&w1l[0], g_s1w1_lo);
    cudaGetSymbolAddress((void**)&w1h[1], g_s2w1_hi);
    cudaGetSymbolAddress((void**)&w1l[1], g_s2w1_lo);
    cudaGetSymbolAddress((void**)&w2h[0], g_s1w2_hi);
    cudaGetSymbolAddress((void**)&w2l[0], g_s1w2_lo);
    cudaGetSymbolAddress((void**)&w2h[1], g_s2w2_hi);
    cudaGetSymbolAddress((void**)&w2l[1], g_s2w2_lo);

    cudaFuncSetAttribute(gemm_mma<0>, cudaFuncAttributeMaxDynamicSharedMemorySize, SM_TOTAL);
    cudaFuncSetAttribute(gemm_mma<1>, cudaFuncAttributeMaxDynamicSharedMemorySize, SM_TOTAL);
    cudaFuncSetAttribute(gemm_mma<2>, cudaFuncAttributeMaxDynamicSharedMemorySize, SM_TOTAL);

    // persistent streams/events for fork-join (created once; deterministic work per call)
    static cudaStream_t st[2];
    static cudaEvent_t evFork, evJ0, evJ1;
    static bool inited = false;
    if (!inited) {
        cudaStreamCreateWithFlags(&st[0], cudaStreamNonBlocking);
        cudaStreamCreateWithFlags(&st[1], cudaStreamNonBlocking);
        cudaEventCreateWithFlags(&evFork, cudaEventDisableTiming);
        cudaEventCreateWithFlags(&evJ0,   cudaEventDisableTiming);
        cudaEventCreateWithFlags(&evJ1,   cudaEventDisableTiming);
        inited = true;
    }

    // ---- shared prologue on origin stream ----
    convert_w1_kernel<<<dim3(K1PAD / 16, HID_ / 16, 2 * NBLK_), 256>>>(
        s1_W1, s2_W1, w1h[0], w1l[0], w1h[1], w1l[1]);
    convert_w2_kernel<<<dim3(K2PAD / 16, N2PAD / 16, 2 * NBLK_), 256>>>(
        s1_W2, s2_W2, w2h[0], w2l[0], w2h[1], w2l[1]);
    init_kernel<<<(B_ * (K1PAD - HALF_) + 255) / 256, 256>>>(jac, xbh, xbl, ysh, ysl);

    // ---- fork ----
    cudaEventRecord(evFork, 0);
    cudaStreamWaitEvent(st[0], evFork, 0);
    cudaStreamWaitEvent(st[1], evFork, 0);

    const dim3 g1Grid(HID_ / TILE_N,  HB_ / TILE_M);   // (8, 16)
    const dim3 g2Grid(N2PAD / TILE_N, HB_ / TILE_M);   // (13, 16)
    const int permGrid = (HB_ * D_ + 255) / 256;

    const size_t W1sz  = (size_t)(HALF_ + CONDN_) * HID_;
    const size_t W1tsz = (size_t)HID_ * K1PAD;
    const size_t W2tsz = (size_t)N2PAD * K2PAD;

    for (int half = 0; half < 2; half++) {
        cudaStream_t s = st[half];
        const size_t off = (size_t)half * HB_;
        const float* xH  = x   + off * D_;
        float* pvH       = pv  + off * D_;
        float* zH        = z   + off * D_;
        float* jacH      = jac + off;
        const int* lH    = l   + off;
        float* xaH = pxa + off * HALF_;
        float* xbH = pxb + off * HALF_;
        __nv_bfloat16* xbhH = xbh + off * K1PAD;
        __nv_bfloat16* xblH = xbl + off * K1PAD;
        __nv_bfloat16* yshH = ysh + off * K1PAD;
        __nv_bfloat16* yslH = ysl + off * K1PAD;
        __nv_bfloat16* hhH  = hh  + off * K2PAD;
        __nv_bfloat16* hlH  = hl  + off * K2PAD;

        for (int k = 0; k < NBLK_; k++) {
            const float* vsrc = (k == 0) ? xH : pvH;
            float* vdst = (k == NBLK_ - 1) ? zH : pvH;

            permute_kernel<<<permGrid, 256, 0, s>>>(
                vsrc, perms + (size_t)k * D_, xaH, xbH, xbhH, xblH);

            // subnet s2: hidden, then output+coupling -> y1 (fp32 vdst + split)
            gemm_mma<0><<<g1Grid, 256, SM_TOTAL, s>>>(
                xbhH, xblH, w1h[1] + k * W1tsz, w1l[1] + k * W1tsz, K1PAD, K1PAD / TILE_K,
                s2_b1 + (size_t)k * HID_, s2_W1 + k * W1sz, lH,
                nullptr, nullptr, nullptr, hhH, hlH);
            gemm_mma<1><<<g2Grid, 256, SM_TOTAL, s>>>(
                hhH, hlH, w2h[1] + k * W2tsz, w2l[1] + k * W2tsz, K2PAD, K2PAD / TILE_K,
                s2_b2 + (size_t)k * D_, nullptr, nullptr,
                xaH, vdst, jacH, yshH, yslH);

            // subnet s1: hidden, then output+coupling -> y2 (fp32 vdst+HALF_)
            gemm_mma<0><<<g1Grid, 256, SM_TOTAL, s>>>(
                yshH, yslH, w1h[0] + k * W1tsz, w1l[0] + k * W1tsz, K1PAD, K1PAD / TILE_K,
                s1_b1 + (size_t)k * HID_, s1_W1 + k * W1sz, lH,
                nullptr, nullptr, nullptr, hhH, hlH);
            gemm_mma<2><<<g2Grid, 256, SM_TOTAL, s>>>(
                hhH, hlH, w2h[0] + k * W2tsz, w2l[0] + k * W2tsz, K2PAD, K2PAD / TILE_K,
                s1_b2 + (size_t)k * D_, nullptr, nullptr,
                xbH, vdst + HALF_, jacH, nullptr, nullptr);
        }
    }

    // ---- join ----
    cudaEventRecord(evJ0, st[0]);
    cudaEventRecord(evJ1, st[1]);
    cudaStreamWaitEvent(0, evJ0, 0);
    cudaStreamWaitEvent(0, evJ1, 0);
}

// round 10
// speedup vs baseline: 1.4378x; 1.0345x over previous
#include <cuda_runtime.h>
#include <cuda_bf16.h>
#include <cstdint>
#include <math.h>

// Problem constants
#define B_     4096
#define D_     784
#define HALF_  392
#define HID_   512
#define CONDN_ 10
#define NBLK_  20

#define K1PAD  416          // 392 padded to 13*32
#define K2PAD  512
#define N2PAD  832          // 416 (s,t)-pairs * 2

// GEMM tiling: CTA 128(M) x 64(N) x 32(K-stage), 8 warps of 32x32, 3-stage pipeline
#define TILE_M 128
#define TILE_N 64
#define TILE_K 32
#define STAGES 3

// smem stage layout (bytes): rows padded 64B->80B for conflict-free ldmatrix
#define SA_ROW   80
#define ST_AHI   0
#define ST_ALO   10240
#define ST_BHI   20480
#define ST_BLO   25600
#define ST_SIZE  30720
#define SM_TOTAL (STAGES * ST_SIZE)

// ---------------- PTX helpers ----------------
__device__ __forceinline__ uint32_t smem_u32(const void* p) {
    uint32_t a;
    asm("{ .reg .u64 t; cvta.to.shared.u64 t, %1; cvt.u32.u64 %0, t; }" : "=r"(a) : "l"(p));
    return a;
}
#define CP_ASYNC16(dst, src) \
    asm volatile("cp.async.cg.shared.global [%0], [%1], 16;" :: "r"(dst), "l"(src))
#define CP_COMMIT() asm volatile("cp.async.commit_group;" ::: "memory")
#define CP_WAIT1()  asm volatile("cp.async.wait_group 1;" ::: "memory")

__device__ __forceinline__ void ldm4(uint32_t& r0, uint32_t& r1, uint32_t& r2, uint32_t& r3,
                                     uint32_t a) {
    asm volatile("ldmatrix.sync.aligned.m8n8.x4.shared.b16 {%0,%1,%2,%3}, [%4];"
                 : "=r"(r0), "=r"(r1), "=r"(r2), "=r"(r3) : "r"(a));
}
__device__ __forceinline__ void mma_bf16(float& c0, float& c1, float& c2, float& c3,
                                         uint32_t a0, uint32_t a1, uint32_t a2, uint32_t a3,
                                         uint32_t b0, uint32_t b1) {
    asm volatile(
        "mma.sync.aligned.m16n8k16.row.col.f32.bf16.bf16.f32 "
        "{%0,%1,%2,%3}, {%4,%5,%6,%7}, {%8,%9}, {%0,%1,%2,%3};"
        : "+f"(c0), "+f"(c1), "+f"(c2), "+f"(c3)
        : "r"(a0), "r"(a1), "r"(a2), "r"(a3), "r"(b0), "r"(b1));
}

// ---------------- device scratch ----------------
__device__ float g_v [B_ * D_];
__device__ float g_xa[B_ * HALF_];
__device__ float g_xb[B_ * HALF_];

__device__ __nv_bfloat16 g_xbh[B_ * K1PAD];
__device__ __nv_bfloat16 g_xbl[B_ * K1PAD];
__device__ __nv_bfloat16 g_ysh[B_ * K1PAD];
__device__ __nv_bfloat16 g_ysl[B_ * K1PAD];
__device__ __nv_bfloat16 g_hh [B_ * K2PAD];
__device__ __nv_bfloat16 g_hl [B_ * K2PAD];

// transposed + split weights: W1t [blk][512][416], W2t interleaved [blk][832][512]
__device__ __nv_bfloat16 g_s1w1_hi[NBLK_ * HID_ * K1PAD];
__device__ __nv_bfloat16 g_s1w1_lo[NBLK_ * HID_ * K1PAD];
__device__ __nv_bfloat16 g_s2w1_hi[NBLK_ * HID_ * K1PAD];
__device__ __nv_bfloat16 g_s2w1_lo[NBLK_ * HID_ * K1PAD];
__device__ __nv_bfloat16 g_s1w2_hi[NBLK_ * N2PAD * K2PAD];
__device__ __nv_bfloat16 g_s1w2_lo[NBLK_ * N2PAD * K2PAD];
__device__ __nv_bfloat16 g_s2w2_hi[NBLK_ * N2PAD * K2PAD];
__device__ __nv_bfloat16 g_s2w2_lo[NBLK_ * N2PAD * K2PAD];

__device__ __forceinline__ void split1(float v, __nv_bfloat16& h, __nv_bfloat16& l) {
    h = __float2bfloat16_rn(v);
    l = __float2bfloat16_rn(v - __bfloat162float(h));
}

// ---------------- small kernels ----------------
// zero jac + zero K-pad columns of split activation buffers
__global__ void init_kernel(float* __restrict__ jac,
                            __nv_bfloat16* __restrict__ xbh, __nv_bfloat16* __restrict__ xbl,
                            __nv_bfloat16* __restrict__ ysh, __nv_bfloat16* __restrict__ ysl) {
    int idx = blockIdx.x * blockDim.x + threadIdx.x;
    if (idx < B_) jac[idx] = 0.f;
    if (idx < B_ * (K1PAD - HALF_)) {
        int i = idx / (K1PAD - HALF_);
        int jj = HALF_ + idx % (K1PAD - HALF_);
        __nv_bfloat16 zz = __float2bfloat16_rn(0.f);
        size_t o = (size_t)i * K1PAD + jj;
        xbh[o] = zz; xbl[o] = zz; ysh[o] = zz; ysl[o] = zz;
    }
}

// permute + split second half (operates on nrows rows; pointers pre-offset)
__global__ void permute_kernel(const float* __restrict__ v,
                               const int* __restrict__ perm,
                               float* __restrict__ xa,
                               float* __restrict__ xb,
                               __nv_bfloat16* __restrict__ xbh,
                               __nv_bfloat16* __restrict__ xbl,
                               int nrows) {
    int idx = blockIdx.x * blockDim.x + threadIdx.x;
    if (idx >= nrows * D_) return;
    int i = idx / D_;
    int j = idx - i * D_;
    float val = v[(size_t)i * D_ + perm[j]];
    if (j < HALF_) {
        xa[(size_t)i * HALF_ + j] = val;
    } else {
        int jj = j - HALF_;
        xb[(size_t)i * HALF_ + jj] = val;
        __nv_bfloat16 h, l;
        split1(val, h, l);
        xbh[(size_t)i * K1PAD + jj] = h;
        xbl[(size_t)i * K1PAD + jj] = l;
    }
}

// transpose + split W1 (both subnets via grid.z): [blk][402][512] -> [blk][512][416]
__global__ void convert_w1_kernel(const float* __restrict__ Ws1, const float* __restrict__ Ws2,
                                  __nv_bfloat16* __restrict__ hi1, __nv_bfloat16* __restrict__ lo1,
                                  __nv_bfloat16* __restrict__ hi2, __nv_bfloat16* __restrict__ lo2) {
    __shared__ float t[16][17];
    int zz = blockIdx.z;
    int sel = zz >= NBLK_;
    int blk = sel ? zz - NBLK_ : zz;
    const float* W = sel ? Ws2 : Ws1;
    __nv_bfloat16* hi = sel ? hi2 : hi1;
    __nv_bfloat16* lo = sel ? lo2 : lo1;
    int bk = blockIdx.x;
    int bn = blockIdx.y;
    int tx = threadIdx.x & 15, ty = threadIdx.x >> 4;
    int k = bk * 16 + ty, n = bn * 16 + tx;
    float v = (k < HALF_) ? W[((size_t)blk * (HALF_ + CONDN_) + k) * HID_ + n] : 0.f;
    t[ty][tx] = v;
    __syncthreads();
    float o = t[tx][ty];
    __nv_bfloat16 h, l;
    split1(o, h, l);
    size_t oidx = ((size_t)blk * HID_ + bn * 16 + ty) * K1PAD + bk * 16 + tx;
    hi[oidx] = h;
    lo[oidx] = l;
}

// transpose + split + (s,t)-interleave W2: [blk][512][784] -> [blk][832][512]
__global__ void convert_w2_kernel(const float* __restrict__ Ws1, const float* __restrict__ Ws2,
                                  __nv_bfloat16* __restrict__ hi1, __nv_bfloat16* __restrict__ lo1,
                                  __nv_bfloat16* __restrict__ hi2, __nv_bfloat16* __restrict__ lo2) {
    __shared__ float t[16][17];
    int zz = blockIdx.z;
    int sel = zz >= NBLK_;
    int blk = sel ? zz - NBLK_ : zz;
    const float* W = sel ? Ws2 : Ws1;
    __nv_bfloat16* hi = sel ? hi2 : hi1;
    __nv_bfloat16* lo = sel ? lo2 : lo1;
    int bk = blockIdx.x;
    int bn = blockIdx.y;
    int tx = threadIdx.x & 15, ty = threadIdx.x >> 4;
    int k = bk * 16 + ty;
    int nOut = bn * 16 + tx;
    int p = nOut >> 1;
    int orig = (nOut & 1) ? (HALF_ + p) : p;
    float v = (p < HALF_) ? W[((size_t)blk * HID_ + k) * D_ + orig] : 0.f;
    t[ty][tx] = v;
    __syncthreads();
    float o = t[tx][ty];
    __nv_bfloat16 h, l;
    split1(o, h, l);
    size_t oidx = ((size_t)blk * N2PAD + bn * 16 + ty) * K2PAD + bk * 16 + tx;
    hi[oidx] = h;
    lo[oidx] = l;
}

// ---------------- fused HMMA GEMM (3-stage pipeline, 1 sync/chunk) ----------------
// MODE 0: hidden layer. C = relu(A@Bt^T + bias + Wcond[392+lab[m]]), write split bf16.
// MODE 1/2: output layer, interleaved (s,t) columns, fused coupling:
//   p = n/2; s = acc(n)+bias[p]; t = acc(n+1)+bias[392+p];
//   ls = 0.636*atan(s); y = exp(ls)*xo[m][p] + t; Yf[m*D_+p] = y; jac[m] += ls;
//   MODE 1 additionally writes split bf16 y (Chi/Clo stride K1PAD).
template<int MODE>
__global__ __launch_bounds__(256, 2)
void gemm_mma(const __nv_bfloat16* __restrict__ Ahi, const __nv_bfloat16* __restrict__ Alo,
              const __nv_bfloat16* __restrict__ Bhi, const __nv_bfloat16* __restrict__ Blo,
              int Ka, int nch,
              const float* __restrict__ bias,
              const float* __restrict__ Wcond, const int* __restrict__ lab,
              const float* __restrict__ xo,
              float* __restrict__ Yf, float* __restrict__ jac,
              __nv_bfloat16* __restrict__ Chi, __nv_bfloat16* __restrict__ Clo) {
    extern __shared__ __align__(128) char sm[];
    const int tid = threadIdx.x;
    const int lane = tid & 31, wid = tid >> 5;
    const int wm = wid & 3, wn = wid >> 2;           // 4x2 warp grid, 32x32 warp tiles
    const int m0 = blockIdx.y * TILE_M, n0 = blockIdx.x * TILE_N;
    const uint32_t sb = smem_u32(sm);

    const int a_row = tid >> 2, a_seg = tid & 3;
    const int b_row = tid >> 2, b_seg = tid & 3;

    float acc[2][4][4];
#pragma unroll
    for (int i = 0; i < 2; i++)
#pragma unroll
        for (int j = 0; j < 4; j++)
#pragma unroll
            for (int q = 0; q < 4; q++) acc[i][j][q] = 0.f;

#define LOAD_STAGE(c, s)                                                                  \
    do {                                                                                  \
        uint32_t st = sb + (s) * ST_SIZE;                                                 \
        const __nv_bfloat16* a0s = Ahi + (size_t)(m0 + a_row) * Ka + (c) * 32 + a_seg * 8;\
        const __nv_bfloat16* a1s = a0s + (size_t)64 * Ka;                                 \
        const __nv_bfloat16* a2s = Alo + (size_t)(m0 + a_row) * Ka + (c) * 32 + a_seg * 8;\
        const __nv_bfloat16* a3s = a2s + (size_t)64 * Ka;                                 \
        CP_ASYNC16(st + ST_AHI + a_row * SA_ROW + a_seg * 16, a0s);                       \
        CP_ASYNC16(st + ST_AHI + (a_row + 64) * SA_ROW + a_seg * 16, a1s);                \
        CP_ASYNC16(st + ST_ALO + a_row * SA_ROW + a_seg * 16, a2s);                       \
        CP_ASYNC16(st + ST_ALO + (a_row + 64) * SA_ROW + a_seg * 16, a3s);                \
        CP_ASYNC16(st + ST_BHI + b_row * SA_ROW + b_seg * 16,                             \
                   Bhi + (size_t)(n0 + b_row) * Ka + (c) * 32 + b_seg * 8);               \
        CP_ASYNC16(st + ST_BLO + b_row * SA_ROW + b_seg * 16,                             \
                   Blo + (size_t)(n0 + b_row) * Ka + (c) * 32 + b_seg * 8);               \
    } while (0)

    LOAD_STAGE(0, 0);
    CP_COMMIT();
    LOAD_STAGE(1, 1);
    CP_COMMIT();

    const uint32_t a_lrow = (lane & 15);
    const uint32_t a_lcol = (lane >> 4) << 4;
    const uint32_t b_lrow = (lane & 7) + ((lane & 16) >> 1);
    const uint32_t b_lcol = (lane & 8) << 1;

    int cs = 0, ls2 = 2;
    for (int c = 0; c < nch; c++) {
        CP_WAIT1();            // in-order retirement: stage c resident
        __syncthreads();       // all warps done with stage (c-1)%3; safe to overwrite
        if (c + 2 < nch) LOAD_STAGE(c + 2, ls2);
        CP_COMMIT();           // commit (possibly empty) keeps group count in sync

        uint32_t st = sb + cs * ST_SIZE;
#pragma unroll
        for (int s = 0; s < 2; s++) {
            uint32_t a[2][2][4];
            uint32_t b[2][4][2];
#pragma unroll
            for (int hl = 0; hl < 2; hl++) {
#pragma unroll
                for (int mm = 0; mm < 2; mm++) {
                    uint32_t ad = st + (hl ? ST_ALO : ST_AHI)
                                + (wm * 32 + mm * 16 + a_lrow) * SA_ROW + a_lcol + s * 32;
                    ldm4(a[hl][mm][0], a[hl][mm][1], a[hl][mm][2], a[hl][mm][3], ad);
                }
#pragma unroll
                for (int nt = 0; nt < 2; nt++) {
                    uint32_t bd = st + (hl ? ST_BLO : ST_BHI)
                                + (wn * 32 + nt * 16 + b_lrow) * SA_ROW + b_lcol + s * 32;
                    ldm4(b[hl][2 * nt][0], b[hl][2 * nt][1],
                         b[hl][2 * nt + 1][0], b[hl][2 * nt + 1][1], bd);
                }
            }
#pragma unroll
            for (int mm = 0; mm < 2; mm++) {
#pragma unroll
                for (int nn = 0; nn < 4; nn++) {
                    float* cc = acc[mm][nn];
                    mma_bf16(cc[0], cc[1], cc[2], cc[3],
                             a[0][mm][0], a[0][mm][1], a[0][mm][2], a[0][mm][3],
                             b[0][nn][0], b[0][nn][1]);
                    mma_bf16(cc[0], cc[1], cc[2], cc[3],
                             a[0][mm][0], a[0][mm][1], a[0][mm][2], a[0][mm][3],
                             b[1][nn][0], b[1][nn][1]);
                    mma_bf16(cc[0], cc[1], cc[2], cc[3],
                             a[1][mm][0], a[1][mm][1], a[1][mm][2], a[1][mm][3],
                             b[0][nn][0], b[0][nn][1]);
                }
            }
        }
        cs = (cs == STAGES - 1) ? 0 : cs + 1;
        ls2 = (ls2 == STAGES - 1) ? 0 : ls2 + 1;
    }
#undef LOAD_STAGE

    // ---- epilogue ----
    const int rbase = lane >> 2;
    const int cbase = (lane & 3) * 2;

    if (MODE == 0) {
#pragma unroll
        for (int mm = 0; mm < 2; mm++) {
#pragma unroll
            for (int h = 0; h < 2; h++) {
                int m = m0 + wm * 32 + mm * 16 + rbase + h * 8;
                const float* wc = Wcond + (size_t)(HALF_ + lab[m]) * HID_;
#pragma unroll
                for (int nn = 0; nn < 4; nn++) {
                    int n = n0 + wn * 32 + nn * 8 + cbase;
                    float v0 = acc[mm][nn][h * 2 + 0] + bias[n] + wc[n];
                    float v1 = acc[mm][nn][h * 2 + 1] + bias[n + 1] + wc[n + 1];
                    v0 = fmaxf(v0, 0.f);
                    v1 = fmaxf(v1, 0.f);
                    __nv_bfloat16 h0, l0, h1, l1;
                    split1(v0, h0, l0);
                    split1(v1, h1, l1);
                    __nv_bfloat162 hp; hp.x = h0; hp.y = h1;
                    __nv_bfloat162 lp; lp.x = l0; lp.y = l1;
                    *reinterpret_cast<__nv_bfloat162*>(Chi + (size_t)m * HID_ + n) = hp;
                    *reinterpret_cast<__nv_bfloat162*>(Clo + (size_t)m * HID_ + n) = lp;
                }
            }
        }
    } else {
#pragma unroll
        for (int mm = 0; mm < 2; mm++) {
#pragma unroll
            for (int h = 0; h < 2; h++) {
                int m = m0 + wm * 32 + mm * 16 + rbase + h * 8;
                float jl = 0.f;
#pragma unroll
                for (int nn = 0; nn < 4; nn++) {
                    int n = n0 + wn * 32 + nn * 8 + cbase;   // always even
                    int p = n >> 1;
                    if (p < HALF_) {
                        float s = acc[mm][nn][h * 2 + 0] + bias[p];
                        float t = acc[mm][nn][h * 2 + 1] + bias[HALF_ + p];
                        float ls = 0.636f * atanf(s);
                        float y = expf(ls) * xo[(size_t)m * HALF_ + p] + t;
                        Yf[(size_t)m * D_ + p] = y;
                        if (MODE == 1) {
                            __nv_bfloat16 yhh, yll;
                            split1(y, yhh, yll);
                            Chi[(size_t)m * K1PAD + p] = yhh;
                            Clo[(size_t)m * K1PAD + p] = yll;
                        }
                        jl += ls;
                    }
                }
                jl += __shfl_xor_sync(0xffffffffu, jl, 1);
                jl += __shfl_xor_sync(0xffffffffu, jl, 2);
                if ((lane & 3) == 0) atomicAdd(&jac[m], jl);
            }
        }
    }
}

// ---------------- host launcher ----------------
extern "C" void kernel_launch(void* const* d_in, const int* in_sizes, int n_in,
                              void* d_out, int out_size) {
    const float* x     = (const float*)d_in[0];
    const int*   l     = (const int*)  d_in[1];
    const int*   perms = (const int*)  d_in[2];
    const float* s1_W1 = (const float*)d_in[3];
    const float* s1_b1 = (const float*)d_in[4];
    const float* s1_W2 = (const float*)d_in[5];
    const float* s1_b2 = (const float*)d_in[6];
    const float* s2_W1 = (const float*)d_in[7];
    const float* s2_b1 = (const float*)d_in[8];
    const float* s2_W2 = (const float*)d_in[9];
    const float* s2_b2 = (const float*)d_in[10];

    float* z   = (float*)d_out;
    float* jac = z + (size_t)B_ * D_;

    float *pv, *pxa, *pxb;
    cudaGetSymbolAddress((void**)&pv,  g_v);
    cudaGetSymbolAddress((void**)&pxa, g_xa);
    cudaGetSymbolAddress((void**)&pxb, g_xb);

    __nv_bfloat16 *xbh, *xbl, *ysh, *ysl, *hh, *hl;
    cudaGetSymbolAddress((void**)&xbh, g_xbh);
    cudaGetSymbolAddress((void**)&xbl, g_xbl);
    cudaGetSymbolAddress((void**)&ysh, g_ysh);
    cudaGetSymbolAddress((void**)&ysl, g_ysl);
    cudaGetSymbolAddress((void**)&hh,  g_hh);
    cudaGetSymbolAddress((void**)&hl,  g_hl);

    __nv_bfloat16 *w1h[2], *w1l[2], *w2h[2], *w2l[2];
    cudaGetSymbolAddress((void**)&w1h[0], g_s1w1_hi);
    cudaGetSymbolAddress((void**)&w1l[0], g_s1w1_lo);
    cudaGetSymbolAddress((void**)&w1h[1], g_s2w1_hi);
    cudaGetSymbolAddress((void**)&w1l[1], g_s2w1_lo);
    cudaGetSymbolAddress((void**)&w2h[0], g_s1w2_hi);
    cudaGetSymbolAddress((void**)&w2l[0], g_s1w2_lo);
    cudaGetSymbolAddress((void**)&w2h[1], g_s2w2_hi);
    cudaGetSymbolAddress((void**)&w2l[1], g_s2w2_lo);

    cudaFuncSetAttribute(gemm_mma<0>, cudaFuncAttributeMaxDynamicSharedMemorySize, SM_TOTAL);
    cudaFuncSetAttribute(gemm_mma<1>, cudaFuncAttributeMaxDynamicSharedMemorySize, SM_TOTAL);
    cudaFuncSetAttribute(gemm_mma<2>, cudaFuncAttributeMaxDynamicSharedMemorySize, SM_TOTAL);

    // persistent side streams/events (created once; deterministic work per call)
    static cudaStream_t st[2];
    static cudaEvent_t evFork, evJ[2];
    static bool inited = false;
    if (!inited) {
        for (int i = 0; i < 2; i++) {
            cudaStreamCreateWithFlags(&st[i], cudaStreamNonBlocking);
            cudaEventCreateWithFlags(&evJ[i], cudaEventDisableTiming);
        }
        cudaEventCreateWithFlags(&evFork, cudaEventDisableTiming);
        inited = true;
    }

    // ---- shared prologue on origin stream ----
    convert_w1_kernel<<<dim3(K1PAD / 16, HID_ / 16, 2 * NBLK_), 256>>>(
        s1_W1, s2_W1, w1h[0], w1l[0], w1h[1], w1l[1]);
    convert_w2_kernel<<<dim3(K2PAD / 16, N2PAD / 16, 2 * NBLK_), 256>>>(
        s1_W2, s2_W2, w2h[0], w2l[0], w2h[1], w2l[1]);
    init_kernel<<<(B_ * (K1PAD - HALF_) + 255) / 256, 256>>>(jac, xbh, xbl, ysh, ysl);

    // ---- fork: side streams wait on prologue; origin stream runs chain 0 ----
    cudaEventRecord(evFork, 0);
    cudaStreamWaitEvent(st[0], evFork, 0);
    cudaStreamWaitEvent(st[1], evFork, 0);

    // chain row split (multiples of TILE_M): 1408 / 1408 / 1280
    const int rowsArr[3] = {1408, 1408, 1280};
    const int offArr[3]  = {0, 1408, 2816};
    cudaStream_t strArr[3] = {(cudaStream_t)0, st[0], st[1]};

    const size_t W1sz  = (size_t)(HALF_ + CONDN_) * HID_;
    const size_t W1tsz = (size_t)HID_ * K1PAD;
    const size_t W2tsz = (size_t)N2PAD * K2PAD;

    for (int c = 0; c < 3; c++) {
        cudaStream_t s = strArr[c];
        const int rows = rowsArr[c];
        const size_t off = (size_t)offArr[c];

        const dim3 g1Grid(HID_ / TILE_N,  rows / TILE_M);
        const dim3 g2Grid(N2PAD / TILE_N, rows / TILE_M);
        const int permGrid = (rows * D_ + 255) / 256;

        const float* xH  = x   + off * D_;
        float* pvH       = pv  + off * D_;
        float* zH        = z   + off * D_;
        float* jacH      = jac + off;
        const int* lH    = l   + off;
        float* xaH = pxa + off * HALF_;
        float* xbH = pxb + off * HALF_;
        __nv_bfloat16* xbhH = xbh + off * K1PAD;
        __nv_bfloat16* xblH = xbl + off * K1PAD;
        __nv_bfloat16* yshH = ysh + off * K1PAD;
        __nv_bfloat16* yslH = ysl + off * K1PAD;
        __nv_bfloat16* hhH  = hh  + off * K2PAD;
        __nv_bfloat16* hlH  = hl  + off * K2PAD;

        for (int k = 0; k < NBLK_; k++) {
            const float* vsrc = (k == 0) ? xH : pvH;
            float* vdst = (k == NBLK_ - 1) ? zH : pvH;

            permute_kernel<<<permGrid, 256, 0, s>>>(
                vsrc, perms + (size_t)k * D_, xaH, xbH, xbhH, xblH, rows);

            // subnet s2: hidden, then output+coupling -> y1 (fp32 vdst + split)
            gemm_mma<0><<<g1Grid, 256, SM_TOTAL, s>>>(
                xbhH, xblH, w1h[1] + k * W1tsz, w1l[1] + k * W1tsz, K1PAD, K1PAD / TILE_K,
                s2_b1 + (size_t)k * HID_, s2_W1 + k * W1sz, lH,
                nullptr, nullptr, nullptr, hhH, hlH);
            gemm_mma<1><<<g2Grid, 256, SM_TOTAL, s>>>(
                hhH, hlH, w2h[1] + k * W2tsz, w2l[1] + k * W2tsz, K2PAD, K2PAD / TILE_K,
                s2_b2 + (size_t)k * D_, nullptr, nullptr,
                xaH, vdst, jacH, yshH, yslH);

            // subnet s1: hidden, then output+coupling -> y2 (fp32 vdst+HALF_)
            gemm_mma<0><<<g1Grid, 256, SM_TOTAL, s>>>(
                yshH, yslH, w1h[0] + k * W1tsz, w1l[0] + k * W1tsz, K1PAD, K1PAD / TILE_K,
                s1_b1 + (size_t)k * HID_, s1_W1 + k * W1sz, lH,
                nullptr, nullptr, nullptr, hhH, hlH);
            gemm_mma<2><<<g2Grid, 256, SM_TOTAL, s>>>(
                hhH, hlH, w2h[0] + k * W2tsz, w2l[0] + k * W2tsz, K2PAD, K2PAD / TILE_K,
                s1_b2 + (size_t)k * D_, nullptr, nullptr,
                xbH, vdst + HALF_, jacH, nullptr, nullptr);
        }
    }

    // ---- join side streams into origin ----
    cudaEventRecord(evJ[0], st[0]);
    cudaEventRecord(evJ[1], st[1]);
    cudaStreamWaitEvent(0, evJ[0], 0);
    cudaStreamWaitEvent(0, evJ[1], 0);
}